// round 2
// baseline (speedup 1.0000x reference)
#include <cuda_runtime.h>
#include <cstdint>

#define BB 256
#define NN 512
#define NP1 513
#define SS 32
#define TT 33
#define DENT 256
#define DK 32
#define DIN 1024
#define DF 256
#define DTY 259
#define HID 32
#define NG 128

#define LOGITS_ELEMS ((size_t)BB * TT * NP1)

// ---------------- scratch (device globals; no allocation allowed) ----------
__device__ float g_padkey[BB * NP1 * DK];   // keys + end row
__device__ float g_func[BB * DF];           // relu(mask_type @ Wfunc^T + b)
__device__ float g_pre10[BB * DF];          // emb0 @ Wfc1^T + b_fc1 + func
__device__ float g_M[DF * DK];              // W_fc1 @ W_embed
__device__ float g_c1[DF];                  // W_fc1 @ b_embed
__device__ int   g_thr[BB * NP1];           // availability threshold per (b,n)
__device__ float g_prefix[BB * TT * DK];    // exclusive prefix of selected keys / N
__device__ float g_gx[BB * TT * NG];        // LSTM input gate pre-activations
__device__ float g_h[BB * TT * HID];        // LSTM hidden per step

__device__ __forceinline__ float sigmoidf_(float x) {
    return 1.0f / (1.0f + __expf(-x));
}
__device__ __forceinline__ float dot4(float4 a, float4 b) {
    return fmaf(a.x, b.x, fmaf(a.y, b.y, fmaf(a.z, b.z, a.w * b.w)));
}

// ---------------- 1) pad_key[b,n,k] = ent[b,n,:] . W_key[k,:] + b_key[k] ----
__global__ void k_key(const float* __restrict__ ent,
                      const float* __restrict__ Wk,
                      const float* __restrict__ bk,
                      const float* __restrict__ endv) {
    __shared__ float sW[32 * 260];
    __shared__ float sbk[32];
    int tid = threadIdx.x;
    for (int idx = tid; idx < 32 * 256; idx += 256) {
        int kk = idx >> 8, d = idx & 255;
        sW[kk * 260 + d] = Wk[idx];
    }
    if (tid < 32) sbk[tid] = bk[tid];
    __syncthreads();
    int lane = tid & 31, w = tid >> 5;
    int stride = gridDim.x * 8;
    for (int row = blockIdx.x * 8 + w; row < BB * NP1; row += stride) {
        int b = row / 513;
        int n = row - b * 513;
        float val;
        if (n == 512) {
            val = endv[lane];
        } else {
            const float4* a4 = reinterpret_cast<const float4*>(ent + ((size_t)(b * 512 + n)) * 256);
            const float4* w4 = reinterpret_cast<const float4*>(&sW[lane * 260]);
            float ax = 0.f, ay = 0.f, az = 0.f, aw = 0.f;
#pragma unroll 8
            for (int d4 = 0; d4 < 64; d4++) {
                float4 a = __ldg(a4 + d4);
                float4 ww = w4[d4];
                ax = fmaf(a.x, ww.x, ax);
                ay = fmaf(a.y, ww.y, ay);
                az = fmaf(a.z, ww.z, az);
                aw = fmaf(a.w, ww.w, aw);
            }
            val = (ax + ay) + (az + aw) + sbk[lane];
        }
        g_padkey[(size_t)row * 32 + lane] = val;
    }
}

// ---------------- 2) func_embed = relu(mask_type @ W_func^T + b_func) ------
__global__ void k_func(const float* __restrict__ mtype,
                       const float* __restrict__ Wf,
                       const float* __restrict__ bf) {
    __shared__ float sW[32 * 261];
    __shared__ float sm[8 * 260];
    __shared__ float sbf[32];
    int tid = threadIdx.x;
    int j0 = blockIdx.x * 32;
    for (int idx = tid; idx < 32 * 259; idx += 256) {
        int jj = idx / 259, d = idx - jj * 259;
        sW[jj * 261 + d] = Wf[(size_t)(j0 + jj) * 259 + d];
    }
    if (tid < 32) sbf[tid] = bf[j0 + tid];
    __syncthreads();
    int jj = tid & 31, bsub = tid >> 5;
    for (int grp = 0; grp < 8; grp++) {
        int bbase = blockIdx.y * 64 + grp * 8;
        for (int idx = tid; idx < 8 * 259; idx += 256) {
            int r = idx / 259, d = idx - r * 259;
            sm[r * 260 + d] = mtype[(size_t)(bbase + r) * 259 + d];
        }
        __syncthreads();
        float acc = sbf[jj];
        const float* mrow = &sm[bsub * 260];
        const float* wrow = &sW[jj * 261];
#pragma unroll 7
        for (int d = 0; d < 259; d++) acc = fmaf(mrow[d], wrow[d], acc);
        g_func[(size_t)(bbase + bsub) * 256 + j0 + jj] = fmaxf(acc, 0.f);
        __syncthreads();
    }
}

// ---------------- 3) M = W_fc1 @ W_embed ; c1 = W_fc1 @ b_embed ------------
__global__ void k_M(const float* __restrict__ Wfc1,
                    const float* __restrict__ Wemb,
                    const float* __restrict__ bemb) {
    __shared__ float se[1024];
    int k = blockIdx.x;  // 0..31 -> M column, 32 -> c1
    int tid = threadIdx.x;
    for (int i = tid; i < 1024; i += 256)
        se[i] = (k < 32) ? Wemb[(size_t)i * 32 + k] : bemb[i];
    __syncthreads();
    int j = tid;
    const float4* wrow = reinterpret_cast<const float4*>(Wfc1 + (size_t)j * 1024);
    const float4* e4 = reinterpret_cast<const float4*>(se);
    float acc = 0.f;
#pragma unroll 8
    for (int i4 = 0; i4 < 256; i4++) acc += dot4(__ldg(wrow + i4), e4[i4]);
    if (k < 32) g_M[j * 32 + k] = acc;
    else        g_c1[j] = acc;
}

// ---------------- 4) pre1_0 = emb0 @ W_fc1^T + b_fc1 + func ----------------
__global__ void k_pre10(const float* __restrict__ emb,
                        const float* __restrict__ Wfc1,
                        const float* __restrict__ bfc1) {
    int w = threadIdx.x >> 5, lane = threadIdx.x & 31;
    int b = blockIdx.y * 8 + w;
    int j = blockIdx.x * 32 + lane;
    const float4* e4 = reinterpret_cast<const float4*>(emb + (size_t)b * 1024);
    const float4* w4 = reinterpret_cast<const float4*>(Wfc1 + (size_t)j * 1024);
    float ax = 0.f, ay = 0.f, az = 0.f, aw = 0.f;
#pragma unroll 8
    for (int i4 = 0; i4 < 256; i4++) {
        float4 e = __ldg(e4 + i4);
        float4 ww = __ldg(w4 + i4);
        ax = fmaf(e.x, ww.x, ax);
        ay = fmaf(e.y, ww.y, ay);
        az = fmaf(e.z, ww.z, az);
        aw = fmaf(e.w, ww.w, aw);
    }
    g_pre10[(size_t)b * 256 + j] = (ax + ay) + (az + aw) + bfc1[j] + g_func[(size_t)b * 256 + j];
}

// ---------------- 5) availability thresholds + selected-key prefix sums ----
__global__ void k_prep(const float* __restrict__ avail,
                       const int* __restrict__ selected) {
    __shared__ int s_thr[NP1];
    int b = blockIdx.x;
    int lane = threadIdx.x;  // 32 threads
    for (int n = lane; n < NP1; n += 32)
        s_thr[n] = (n == 512) ? 33 : (avail[(size_t)b * 512 + n] > 0.5f ? 33 : -1);
    __syncwarp();
    float acc = 0.f;
    const float inv_n = 1.0f / 512.0f;
    for (int t = 0; t < 32; t++) {
        g_prefix[((size_t)b * 33 + t) * 32 + lane] = acc;
        int sel = selected[b * 32 + t];
        acc += g_padkey[((size_t)b * 513 + sel) * 32 + lane] * inv_n;
        if (lane == 0) {
            int v = s_thr[sel];
            if (v < 0 || v >= 32) s_thr[sel] = t;  // first selection time
        }
        __syncwarp();
    }
    g_prefix[((size_t)b * 33 + 32) * 32 + lane] = acc;
    for (int n = lane; n < NP1; n += 32)
        g_thr[(size_t)b * 513 + n] = s_thr[n];
}

// ---------------- 6) LSTM input pre-activations for all (b,t) --------------
__global__ void k_gatesx(const float* __restrict__ Wfc2,
                         const float* __restrict__ bfc2,
                         const float* __restrict__ Wih,
                         const float* __restrict__ bih,
                         const float* __restrict__ bhh) {
    __shared__ float s_p[32];
    __shared__ float s_a[256];
    __shared__ float s_part[8 * 33];
    __shared__ float s_x[32];
    int t = blockIdx.x, b = blockIdx.y, tid = threadIdx.x;
    if (tid < 32) s_p[tid] = g_prefix[((size_t)b * 33 + t) * 32 + tid];
    __syncthreads();
    {   // relu(pre1_0 + t*c1 + prefix @ M^T)
        int j = tid;
        float acc = g_pre10[(size_t)b * 256 + j] + (float)t * g_c1[j];
        const float4* m4 = reinterpret_cast<const float4*>(g_M + j * 32);
        const float4* p4 = reinterpret_cast<const float4*>(s_p);
#pragma unroll
        for (int q = 0; q < 8; q++) acc += dot4(__ldg(m4 + q), p4[q]);
        s_a[j] = fmaxf(acc, 0.f);
    }
    __syncthreads();
    {   // x = relu_vec @ W_fc2^T (split-K over 8 parts)
        int i = tid & 31, part = tid >> 5;
        const float4* wf = reinterpret_cast<const float4*>(Wfc2 + (size_t)i * 256 + part * 32);
        const float4* a4 = reinterpret_cast<const float4*>(s_a + part * 32);
        float s = 0.f;
#pragma unroll
        for (int q = 0; q < 8; q++) s += dot4(__ldg(wf + q), a4[q]);
        s_part[part * 33 + i] = s;
    }
    __syncthreads();
    if (tid < 32) {
        float x = bfc2[tid];
#pragma unroll
        for (int p = 0; p < 8; p++) x += s_part[p * 33 + tid];
        s_x[tid] = x;
    }
    __syncthreads();
    if (tid < 128) {  // gates_x = x @ W_ih^T + b_ih + b_hh
        int g = tid;
        float acc = bih[g] + bhh[g];
        const float4* wi = reinterpret_cast<const float4*>(Wih + (size_t)g * 32);
        const float4* x4 = reinterpret_cast<const float4*>(s_x);
#pragma unroll
        for (int q = 0; q < 8; q++) acc += dot4(__ldg(wi + q), x4[q]);
        g_gx[((size_t)b * 33 + t) * 128 + g] = acc;
    }
}

// ---------------- 7) LSTM recurrence (only true sequential part) -----------
__global__ void k_lstm(const float* __restrict__ Whh) {
    __shared__ float sW[128 * 33];
    __shared__ float s_h[32];
    __shared__ float s_c[32];
    __shared__ float s_g[128];
    int b = blockIdx.x, tid = threadIdx.x;  // 128 threads
    for (int idx = tid; idx < 128 * 32; idx += 128) {
        int g = idx >> 5, kk = idx & 31;
        sW[g * 33 + kk] = Whh[idx];
    }
    if (tid < 32) { s_h[tid] = 0.f; s_c[tid] = 0.f; }
    __syncthreads();
    for (int t = 0; t < 33; t++) {
        float gg = g_gx[((size_t)b * 33 + t) * 128 + tid];
        const float* wrow = &sW[tid * 33];
#pragma unroll
        for (int kk = 0; kk < 32; kk++) gg = fmaf(wrow[kk], s_h[kk], gg);
        s_g[tid] = gg;
        __syncthreads();
        if (tid < 32) {
            float ig = sigmoidf_(s_g[tid]);
            float fg = sigmoidf_(s_g[32 + tid]);
            float gt = tanhf(s_g[64 + tid]);
            float og = sigmoidf_(s_g[96 + tid]);
            float c = fmaf(fg, s_c[tid], ig * gt);
            float h = og * tanhf(c);
            s_c[tid] = c;
            s_h[tid] = h;
            g_h[((size_t)b * 33 + t) * 32 + tid] = h;
        }
        __syncthreads();
    }
}

// ---------------- 8) logits[b,t,n] = h_t . key_n - mask --------------------
__global__ void k_logits(float* __restrict__ out) {
    __shared__ float s_h[33 * 32];
    __shared__ float s_key[128 * 36];
    int b = blockIdx.y, n0 = blockIdx.x * 128, tid = threadIdx.x;
    for (int idx = tid; idx < 33 * 32; idx += 256)
        s_h[idx] = g_h[(size_t)b * (33 * 32) + idx];
    int nmax = NP1 - n0; if (nmax > 128) nmax = 128;
    for (int idx = tid; idx < nmax * 32; idx += 256) {
        int r = idx >> 5, kk = idx & 31;
        s_key[r * 36 + kk] = g_padkey[((size_t)(b * 513 + n0)) * 32 + idx];
    }
    __syncthreads();
    int nn = tid & 127, ts = tid >> 7;
    if (nn < nmax) {
        int n = n0 + nn;
        float4 kr[8];
        const float4* k4 = reinterpret_cast<const float4*>(&s_key[nn * 36]);
#pragma unroll
        for (int q = 0; q < 8; q++) kr[q] = k4[q];
        int thr = g_thr[(size_t)b * 513 + n];
        for (int t = ts; t < 33; t += 2) {
            const float4* h4 = reinterpret_cast<const float4*>(&s_h[t * 32]);
            float acc = 0.f;
#pragma unroll
            for (int q = 0; q < 8; q++) acc += dot4(h4[q], kr[q]);
            out[((size_t)b * 33 + t) * 513 + n] = acc - (t > thr ? 1e9f : 0.f);
        }
    }
}

// ---------------- 9) final emb output ---------------------------------------
__global__ void k_emb(float* __restrict__ out,
                      const float* __restrict__ emb0,
                      const float* __restrict__ Wemb,
                      const float* __restrict__ bemb) {
    __shared__ float s_p[32];
    int b = blockIdx.x, tid = threadIdx.x;
    if (tid < 32) s_p[tid] = g_prefix[((size_t)b * 33 + 32) * 32 + tid];
    __syncthreads();
    const float4* p4 = reinterpret_cast<const float4*>(s_p);
#pragma unroll
    for (int q = 0; q < 4; q++) {
        int i = q * 256 + tid;
        const float4* we = reinterpret_cast<const float4*>(Wemb + (size_t)i * 32);
        float acc = __ldg(&emb0[(size_t)b * 1024 + i]) + 32.0f * __ldg(&bemb[i]);
#pragma unroll
        for (int r = 0; r < 8; r++) acc += dot4(__ldg(we + r), p4[r]);
        out[LOGITS_ELEMS + (size_t)b * 1024 + i] = acc;
    }
}

// ---------------- launch -----------------------------------------------------
extern "C" void kernel_launch(void* const* d_in, const int* in_sizes, int n_in,
                              void* d_out, int out_size) {
    const float* embedding = (const float*)d_in[0];
    const float* type_mask = (const float*)d_in[1];
    const float* avail     = (const float*)d_in[2];
    const float* ent       = (const float*)d_in[3];
    const int*   selected  = (const int*)d_in[4];
    const float* endv      = (const float*)d_in[5];
    const float* W_key  = (const float*)d_in[6];
    const float* b_key  = (const float*)d_in[7];
    const float* W_func = (const float*)d_in[8];
    const float* b_func = (const float*)d_in[9];
    const float* W_fc1  = (const float*)d_in[10];
    const float* b_fc1  = (const float*)d_in[11];
    const float* W_fc2  = (const float*)d_in[12];
    const float* b_fc2  = (const float*)d_in[13];
    const float* W_emb  = (const float*)d_in[14];
    const float* b_emb  = (const float*)d_in[15];
    const float* W_ih   = (const float*)d_in[16];
    const float* b_ih   = (const float*)d_in[17];
    const float* W_hh   = (const float*)d_in[18];
    const float* b_hh   = (const float*)d_in[19];
    float* out = (float*)d_out;

    k_key<<<512, 256>>>(ent, W_key, b_key, endv);
    k_func<<<dim3(8, 4), 256>>>(type_mask, W_func, b_func);
    k_M<<<33, 256>>>(W_fc1, W_emb, b_emb);
    k_pre10<<<dim3(8, 32), 256>>>(embedding, W_fc1, b_fc1);
    k_prep<<<256, 32>>>(avail, selected);
    k_gatesx<<<dim3(33, 256), 256>>>(W_fc2, b_fc2, W_ih, b_ih, b_hh);
    k_lstm<<<256, 128>>>(W_hh);
    k_logits<<<dim3(5, 256), 256>>>(out);
    k_emb<<<256, 256>>>(out, embedding, W_emb, b_emb);
}

// round 7
// speedup vs baseline: 1.6634x; 1.6634x over previous
#include <cuda_runtime.h>
#include <cuda_bf16.h>
#include <cstdint>

#define BB 256
#define NN 512
#define NP1 513
#define TT 33
#define DK 32
#define DIN 1024
#define DF 256
#define DTY 259
#define NG 128

#define LOGITS_ELEMS ((size_t)BB * TT * NP1)

// ---------------- scratch (device globals; no allocation allowed) ----------
__device__ float g_padkey[BB * NP1 * DK];   // keys + end row
__device__ float g_func[BB * DF];           // relu(mask_type @ Wfunc^T + b)
__device__ float g_pre10[BB * DF];          // emb0 @ Wfc1^T + b_fc1
__device__ float g_M[DF * DK];              // W_fc1 @ W_embed
__device__ float g_c1[DF];                  // W_fc1 @ b_embed
__device__ float g_wcomb[NG * DF];          // W_ih @ W_fc2
__device__ float g_gbias[NG];               // W_ih@b_fc2 + b_ih + b_hh
__device__ int   g_thr[BB * NP1];           // first-selected-step per (b,n)
__device__ float g_prefix[BB * TT * DK];    // exclusive prefix of selected keys / N
__device__ float g_relua[BB * TT * DF];     // relu(fc1 pre-activations)
__device__ float g_gx[BB * TT * NG];        // LSTM gate pre-activations
__device__ float g_h[BB * TT * 32];         // LSTM hidden per step

__device__ __forceinline__ float sigmoidf_(float x) {
    return 1.0f / (1.0f + __expf(-x));
}
__device__ __forceinline__ float dot4(float4 a, float4 b) {
    return fmaf(a.x, b.x, fmaf(a.y, b.y, fmaf(a.z, b.z, a.w * b.w)));
}

// pack2(lo, hi): bf16x2 with 'lo' in bits[15:0]
__device__ __forceinline__ uint32_t pack2(float lo, float hi) {
    uint32_t r;
    asm("cvt.rn.bf16x2.f32 %0, %1, %2;" : "=r"(r) : "f"(hi), "f"(lo));
    return r;
}
// split x0,x1 into bf16 hi word + bf16 lo-residual word
__device__ __forceinline__ void cvt_hilo(float x0, float x1, uint32_t& h, uint32_t& l) {
    h = pack2(x0, x1);
    float h0 = __uint_as_float(h << 16);
    float h1 = __uint_as_float(h & 0xffff0000u);
    l = pack2(x0 - h0, x1 - h1);
}
__device__ __forceinline__ void mma16816(float* d, uint32_t a0, uint32_t a1,
                                         uint32_t a2, uint32_t a3,
                                         uint32_t b0, uint32_t b1) {
    asm volatile(
        "mma.sync.aligned.m16n8k16.row.col.f32.bf16.bf16.f32 "
        "{%0,%1,%2,%3},{%4,%5,%6,%7},{%8,%9},{%0,%1,%2,%3};"
        : "+f"(d[0]), "+f"(d[1]), "+f"(d[2]), "+f"(d[3])
        : "r"(a0), "r"(a1), "r"(a2), "r"(a3), "r"(b0), "r"(b1));
}

// ================= generic fp32-in / fp32-out GEMM on tensor cores ==========
// C[m, n] = sum_k A[m,k] * Bw[n,k] + bias[n]   (optional relu)
// A row-major [M,K], Bw row-major [N,K]. M % BM == 0, N == gridDim.y*BN.
// bf16 hi/lo split: 3 MMAs per k-chunk. KEYREMAP: out row = r + r/512.
// Handles K % 4 != 0 (misaligned rows) via scalar loads.
template <int WARPS_M, int WARPS_N, int BK, bool RELU, bool KEYREMAP>
__global__ void __launch_bounds__(256, 1)
gemm_bf16s(const float* __restrict__ A, const float* __restrict__ Bw,
           float* __restrict__ C, const float* __restrict__ bias,
           int K, int ldc) {
    constexpr int BM = WARPS_M * 16;
    constexpr int BN = WARPS_N * 32;
    constexpr int WPR = BK / 2;  // u32 words per tile row
    extern __shared__ uint32_t smem_u[];
    uint32_t* sAh = smem_u;
    uint32_t* sAl = sAh + BM * WPR;
    uint32_t* sBh = sAl + BM * WPR;
    uint32_t* sBl = sBh + BN * WPR;

    const int tid = threadIdx.x;
    const int wid = tid >> 5, lane = tid & 31;
    const int g = lane >> 2, tig = lane & 3;
    const int wm = wid % WARPS_M, wn = wid / WARPS_M;
    const int m0 = blockIdx.x * BM;
    const int n0 = blockIdx.y * BN;
    const bool k4 = ((K & 3) == 0);

    float acc[4][4];
    for (int i = 0; i < 4; i++)
        for (int j = 0; j < 4; j++) acc[i][j] = 0.f;

    const int kiters = (K + BK - 1) / BK;
    for (int kt = 0; kt < kiters; kt++) {
        const int k0 = kt * BK;
        // ---- load A tile (fp32 -> bf16 hi/lo, swizzled) ----
        for (int idx = tid; idx < BM * (BK / 4); idx += 256) {
            int row = idx / (BK / 4), c4 = idx % (BK / 4);
            int gc = k0 + c4 * 4;
            float4 v = make_float4(0.f, 0.f, 0.f, 0.f);
            const float* ap = A + (size_t)(m0 + row) * K + gc;
            if (k4 && gc + 4 <= K) {
                v = *(const float4*)ap;
            } else {
                if (gc + 0 < K) v.x = ap[0];
                if (gc + 1 < K) v.y = ap[1];
                if (gc + 2 < K) v.z = ap[2];
                if (gc + 3 < K) v.w = ap[3];
            }
            uint32_t h0, l0, h1, l1;
            cvt_hilo(v.x, v.y, h0, l0);
            cvt_hilo(v.z, v.w, h1, l1);
            int w0 = (c4 * 2) ^ ((row & 7) << 2);
            *(uint2*)&sAh[row * WPR + w0] = make_uint2(h0, h1);
            *(uint2*)&sAl[row * WPR + w0] = make_uint2(l0, l1);
        }
        // ---- load B tile ----
        for (int idx = tid; idx < BN * (BK / 4); idx += 256) {
            int row = idx / (BK / 4), c4 = idx % (BK / 4);
            int gc = k0 + c4 * 4;
            float4 v = make_float4(0.f, 0.f, 0.f, 0.f);
            const float* bp = Bw + (size_t)(n0 + row) * K + gc;
            if (k4 && gc + 4 <= K) {
                v = *(const float4*)bp;
            } else {
                if (gc + 0 < K) v.x = bp[0];
                if (gc + 1 < K) v.y = bp[1];
                if (gc + 2 < K) v.z = bp[2];
                if (gc + 3 < K) v.w = bp[3];
            }
            uint32_t h0, l0, h1, l1;
            cvt_hilo(v.x, v.y, h0, l0);
            cvt_hilo(v.z, v.w, h1, l1);
            int w0 = (c4 * 2) ^ ((row & 7) << 2);
            *(uint2*)&sBh[row * WPR + w0] = make_uint2(h0, h1);
            *(uint2*)&sBl[row * WPR + w0] = make_uint2(l0, l1);
        }
        __syncthreads();
        // ---- compute ----
        const int sw = g << 2;
        const int ra0 = (wm * 16 + g) * WPR;
        const int ra1 = (wm * 16 + g + 8) * WPR;
#pragma unroll 4
        for (int c = 0; c < BK / 16; c++) {
            int ws0 = c * 8 + tig;
            uint32_t a0h = sAh[ra0 + (ws0 ^ sw)];
            uint32_t a1h = sAh[ra1 + (ws0 ^ sw)];
            uint32_t a2h = sAh[ra0 + ((ws0 + 4) ^ sw)];
            uint32_t a3h = sAh[ra1 + ((ws0 + 4) ^ sw)];
            uint32_t a0l = sAl[ra0 + (ws0 ^ sw)];
            uint32_t a1l = sAl[ra1 + (ws0 ^ sw)];
            uint32_t a2l = sAl[ra0 + ((ws0 + 4) ^ sw)];
            uint32_t a3l = sAl[ra1 + ((ws0 + 4) ^ sw)];
#pragma unroll
            for (int nt = 0; nt < 4; nt++) {
                int rb = (wn * 32 + nt * 8 + g) * WPR;
                uint32_t b0h = sBh[rb + (ws0 ^ sw)];
                uint32_t b1h = sBh[rb + ((ws0 + 4) ^ sw)];
                uint32_t b0l = sBl[rb + (ws0 ^ sw)];
                uint32_t b1l = sBl[rb + ((ws0 + 4) ^ sw)];
                mma16816(acc[nt], a0h, a1h, a2h, a3h, b0h, b1h);
                mma16816(acc[nt], a0h, a1h, a2h, a3h, b0l, b1l);
                mma16816(acc[nt], a0l, a1l, a2l, a3l, b0h, b1h);
            }
        }
        __syncthreads();
    }
    // ---- epilogue ----
#pragma unroll
    for (int nt = 0; nt < 4; nt++) {
        int col = n0 + wn * 32 + nt * 8 + 2 * tig;
        float b0v = __ldg(&bias[col]);
        float b1v = __ldg(&bias[col + 1]);
#pragma unroll
        for (int half = 0; half < 2; half++) {
            int r = m0 + wm * 16 + g + half * 8;
            int orow = KEYREMAP ? (r + (r >> 9)) : r;
            float x0 = acc[nt][half * 2 + 0] + b0v;
            float x1 = acc[nt][half * 2 + 1] + b1v;
            if (RELU) { x0 = fmaxf(x0, 0.f); x1 = fmaxf(x1, 0.f); }
            *(float2*)&C[(size_t)orow * ldc + col] = make_float2(x0, x1);
        }
    }
}

// ---------------- M = W_fc1 @ W_embed ; c1 = W_fc1 @ b_embed ------------
__global__ void k_M(const float* __restrict__ Wfc1,
                    const float* __restrict__ Wemb,
                    const float* __restrict__ bemb) {
    __shared__ float se[1024];
    int k = blockIdx.x;  // 0..31 -> M column, 32 -> c1
    int tid = threadIdx.x;
    for (int i = tid; i < 1024; i += 256)
        se[i] = (k < 32) ? Wemb[(size_t)i * 32 + k] : bemb[i];
    __syncthreads();
    int j = tid;
    const float4* wrow = reinterpret_cast<const float4*>(Wfc1 + (size_t)j * 1024);
    const float4* e4 = reinterpret_cast<const float4*>(se);
    float acc = 0.f;
#pragma unroll 8
    for (int i4 = 0; i4 < 256; i4++) acc += dot4(__ldg(wrow + i4), e4[i4]);
    if (k < 32) g_M[j * 32 + k] = acc;
    else        g_c1[j] = acc;
}

// ---------------- Wcomb = W_ih @ W_fc2 ; gbias --------------------------
__global__ void k_wcomb(const float* __restrict__ Wfc2,
                        const float* __restrict__ bfc2,
                        const float* __restrict__ Wih,
                        const float* __restrict__ bih,
                        const float* __restrict__ bhh) {
    __shared__ float sWih[32];
    int gi = blockIdx.x;  // 0..127
    int tid = threadIdx.x;
    if (tid < 32) sWih[tid] = Wih[gi * 32 + tid];
    __syncthreads();
    float acc = 0.f;
#pragma unroll
    for (int k = 0; k < 32; k++) acc = fmaf(sWih[k], __ldg(&Wfc2[k * 256 + tid]), acc);
    g_wcomb[gi * 256 + tid] = acc;
    if (tid == 0) {
        float b = bih[gi] + bhh[gi];
#pragma unroll
        for (int k = 0; k < 32; k++) b = fmaf(sWih[k], bfc2[k], b);
        g_gbias[gi] = b;
    }
}

// -------- availability thresholds + selected-key prefix sums + end rows ----
__global__ void k_prep(const float* __restrict__ avail,
                       const int* __restrict__ selected,
                       const float* __restrict__ endv) {
    __shared__ int s_thr[NP1];
    int b = blockIdx.x;
    int lane = threadIdx.x;  // 32 threads
    g_padkey[((size_t)b * NP1 + 512) * 32 + lane] = endv[lane];
    for (int n = lane; n < NP1; n += 32)
        s_thr[n] = (n == 512) ? 33 : (avail[(size_t)b * 512 + n] > 0.5f ? 33 : -1);
    __syncwarp();
    float acc = 0.f;
    const float inv_n = 1.0f / 512.0f;
    for (int t = 0; t < 32; t++) {
        g_prefix[((size_t)b * TT + t) * 32 + lane] = acc;
        int sel = selected[b * 32 + t];
        acc += g_padkey[((size_t)b * NP1 + sel) * 32 + lane] * inv_n;
        if (lane == 0) {
            int v = s_thr[sel];
            if (v < 0 || v >= 32) s_thr[sel] = t;  // first selection time
        }
        __syncwarp();
    }
    g_prefix[((size_t)b * TT + 32) * 32 + lane] = acc;
    for (int n = lane; n < NP1; n += 32)
        g_thr[(size_t)b * NP1 + n] = s_thr[n];
}

// -------- relu_a[b,t,:] = relu(pre10 + func + t*c1 + prefix_t @ M^T) --------
__global__ void k_gA() {
    __shared__ float sp[TT * 32];
    int b = blockIdx.x, tid = threadIdx.x;  // 256 threads
    for (int i = tid; i < TT * 32; i += 256) sp[i] = g_prefix[(size_t)b * TT * 32 + i];
    float pre = g_pre10[(size_t)b * 256 + tid] + g_func[(size_t)b * 256 + tid];
    float c1 = g_c1[tid];
    float m[32];
    const float4* mr = reinterpret_cast<const float4*>(g_M + tid * 32);
#pragma unroll
    for (int q = 0; q < 8; q++) {
        float4 v = __ldg(mr + q);
        m[q * 4 + 0] = v.x; m[q * 4 + 1] = v.y; m[q * 4 + 2] = v.z; m[q * 4 + 3] = v.w;
    }
    __syncthreads();
    for (int t = 0; t < TT; t++) {
        float acc = fmaf((float)t, c1, pre);
        const float* p = &sp[t * 32];
#pragma unroll
        for (int k = 0; k < 32; k++) acc = fmaf(m[k], p[k], acc);
        g_relua[((size_t)b * TT + t) * 256 + tid] = fmaxf(acc, 0.f);
    }
}

// ---------------- LSTM recurrence (only true sequential part) -----------
__global__ void k_lstm(const float* __restrict__ Whh) {
    __shared__ float sW[128 * 33];
    __shared__ float s_h[32];
    __shared__ float s_c[32];
    __shared__ float s_g[128];
    int b = blockIdx.x, tid = threadIdx.x;  // 128 threads
    for (int idx = tid; idx < 128 * 32; idx += 128) {
        int gg2 = idx >> 5, kk = idx & 31;
        sW[gg2 * 33 + kk] = Whh[idx];
    }
    if (tid < 32) { s_h[tid] = 0.f; s_c[tid] = 0.f; }
    __syncthreads();
    for (int t = 0; t < TT; t++) {
        float gg = g_gx[((size_t)b * TT + t) * 128 + tid];
        const float* wrow = &sW[tid * 33];
#pragma unroll
        for (int kk = 0; kk < 32; kk++) gg = fmaf(wrow[kk], s_h[kk], gg);
        s_g[tid] = gg;
        __syncthreads();
        if (tid < 32) {
            float ig = sigmoidf_(s_g[tid]);
            float fg = sigmoidf_(s_g[32 + tid]);
            float gt = tanhf(s_g[64 + tid]);
            float og = sigmoidf_(s_g[96 + tid]);
            float c = fmaf(fg, s_c[tid], ig * gt);
            float h = og * tanhf(c);
            s_c[tid] = c;
            s_h[tid] = h;
            g_h[((size_t)b * TT + t) * 32 + tid] = h;
        }
        __syncthreads();
    }
}

// ---------------- logits[b,t,n] = h_t . key_n - mask --------------------
__global__ void k_logits(float* __restrict__ out) {
    __shared__ float s_h[TT * 32];
    __shared__ float s_key[128 * 36];
    int b = blockIdx.y, n0 = blockIdx.x * 128, tid = threadIdx.x;
    for (int idx = tid; idx < TT * 32; idx += 256)
        s_h[idx] = g_h[(size_t)b * (TT * 32) + idx];
    int nmax = NP1 - n0; if (nmax > 128) nmax = 128;
    for (int idx = tid; idx < nmax * 32; idx += 256) {
        int r = idx >> 5, kk = idx & 31;
        s_key[r * 36 + kk] = g_padkey[((size_t)(b * NP1 + n0)) * 32 + idx];
    }
    __syncthreads();
    int nn = tid & 127, ts = tid >> 7;
    if (nn < nmax) {
        int n = n0 + nn;
        float4 kr[8];
        const float4* k4 = reinterpret_cast<const float4*>(&s_key[nn * 36]);
#pragma unroll
        for (int q = 0; q < 8; q++) kr[q] = k4[q];
        int thr = g_thr[(size_t)b * NP1 + n];
        for (int t = ts; t < TT; t += 2) {
            const float4* h4 = reinterpret_cast<const float4*>(&s_h[t * 32]);
            float acc = 0.f;
#pragma unroll
            for (int q = 0; q < 8; q++) acc += dot4(h4[q], kr[q]);
            out[((size_t)b * TT + t) * NP1 + n] = acc - (t > thr ? 1e9f : 0.f);
        }
    }
}

// ---------------- final emb output ---------------------------------------
__global__ void k_emb(float* __restrict__ out,
                      const float* __restrict__ emb0,
                      const float* __restrict__ Wemb,
                      const float* __restrict__ bemb) {
    __shared__ float s_p[32];
    int b = blockIdx.x, tid = threadIdx.x;
    if (tid < 32) s_p[tid] = g_prefix[((size_t)b * TT + 32) * 32 + tid];
    __syncthreads();
    const float4* p4 = reinterpret_cast<const float4*>(s_p);
#pragma unroll
    for (int q = 0; q < 4; q++) {
        int i = q * 256 + tid;
        const float4* we = reinterpret_cast<const float4*>(Wemb + (size_t)i * 32);
        float acc = __ldg(&emb0[(size_t)b * 1024 + i]) + 32.0f * __ldg(&bemb[i]);
#pragma unroll
        for (int r = 0; r < 8; r++) acc += dot4(__ldg(we + r), p4[r]);
        out[LOGITS_ELEMS + (size_t)b * 1024 + i] = acc;
    }
}

// ---------------- launch -----------------------------------------------------
extern "C" void kernel_launch(void* const* d_in, const int* in_sizes, int n_in,
                              void* d_out, int out_size) {
    const float* embedding = (const float*)d_in[0];
    const float* type_mask = (const float*)d_in[1];
    const float* avail     = (const float*)d_in[2];
    const float* ent       = (const float*)d_in[3];
    const int*   selected  = (const int*)d_in[4];
    const float* endv      = (const float*)d_in[5];
    const float* W_key  = (const float*)d_in[6];
    const float* b_key  = (const float*)d_in[7];
    const float* W_func = (const float*)d_in[8];
    const float* b_func = (const float*)d_in[9];
    const float* W_fc1  = (const float*)d_in[10];
    const float* b_fc1  = (const float*)d_in[11];
    const float* W_fc2  = (const float*)d_in[12];
    const float* b_fc2  = (const float*)d_in[13];
    const float* W_emb  = (const float*)d_in[14];
    const float* b_emb  = (const float*)d_in[15];
    const float* W_ih   = (const float*)d_in[16];
    const float* b_ih   = (const float*)d_in[17];
    const float* W_hh   = (const float*)d_in[18];
    const float* b_hh   = (const float*)d_in[19];
    float* out = (float*)d_out;

    // smem sizes: CFG1 (8,1,256): 2*128*(128+32)*4 = 163840 B
    //             CFG2 (4,2,128): 2*64*(64+64)*4  = 65536 B
    const int SM1 = 163840, SM2 = 65536;
    cudaFuncSetAttribute(gemm_bf16s<8, 1, 256, false, true>,
                         cudaFuncAttributeMaxDynamicSharedMemorySize, SM1);
    cudaFuncSetAttribute(gemm_bf16s<8, 1, 256, false, false>,
                         cudaFuncAttributeMaxDynamicSharedMemorySize, SM1);
    cudaFuncSetAttribute(gemm_bf16s<4, 2, 128, false, false>,
                         cudaFuncAttributeMaxDynamicSharedMemorySize, SM2);
    cudaFuncSetAttribute(gemm_bf16s<4, 2, 128, true, false>,
                         cudaFuncAttributeMaxDynamicSharedMemorySize, SM2);

    float* padkey; cudaGetSymbolAddress((void**)&padkey, g_padkey);
    float* pre10;  cudaGetSymbolAddress((void**)&pre10, g_pre10);
    float* funcb;  cudaGetSymbolAddress((void**)&funcb, g_func);
    float* relua;  cudaGetSymbolAddress((void**)&relua, g_relua);
    float* wcomb;  cudaGetSymbolAddress((void**)&wcomb, g_wcomb);
    float* gbias;  cudaGetSymbolAddress((void**)&gbias, g_gbias);
    float* gx;     cudaGetSymbolAddress((void**)&gx, g_gx);

    // 1) pad_key = ent @ W_key^T + b_key  (rows remapped to b*513+n)
    gemm_bf16s<8, 1, 256, false, true>
        <<<dim3(BB * NN / 128, 1), 256, SM1>>>(ent, W_key, padkey, b_key, 256, 32);
    // 2) pre10 = emb0 @ W_fc1^T + b_fc1
    gemm_bf16s<4, 2, 128, false, false>
        <<<dim3(4, 4), 256, SM2>>>(embedding, W_fc1, pre10, b_fc1, 1024, 256);
    // 3) func = relu(type_mask @ W_func^T + b_func)  (K=259 -> scalar loads)
    gemm_bf16s<4, 2, 128, true, false>
        <<<dim3(4, 4), 256, SM2>>>(type_mask, W_func, funcb, b_func, DTY, 256);
    // 4) small precomputes
    k_M<<<33, 256>>>(W_fc1, W_emb, b_emb);
    k_wcomb<<<128, 256>>>(W_fc2, b_fc2, W_ih, b_ih, b_hh);
    // 5) thresholds + prefixes + end rows (needs padkey)
    k_prep<<<BB, 32>>>(avail, selected, endv);
    // 6) relu_a for all (b,t)
    k_gA<<<BB, 256>>>();
    // 7) gates = relu_a @ Wcomb^T + gbias
    gemm_bf16s<8, 1, 256, false, false>
        <<<dim3(BB * TT / 128, 4), 256, SM1>>>(relua, wcomb, gx, gbias, 256, 128);
    // 8) LSTM recurrence
    k_lstm<<<BB, 128>>>(W_hh);
    // 9) logits + final emb
    k_logits<<<dim3(5, BB), 256>>>(out);
    k_emb<<<BB, 256>>>(out, embedding, W_emb, b_emb);
}

// round 8
// speedup vs baseline: 2.4563x; 1.4767x over previous
#include <cuda_runtime.h>
#include <cuda_bf16.h>
#include <cstdint>

#define BB 256
#define NN 512
#define NP1 513
#define TT 33
#define DK 32
#define DIN 1024
#define DF 256
#define DTY 259
#define NG 128

#define LOGITS_ELEMS ((size_t)BB * TT * NP1)

// ---------------- scratch (device globals; no allocation allowed) ----------
__device__ float g_padkey[BB * NP1 * DK];   // keys + end row
__device__ float g_func[BB * DF];           // relu(mask_type @ Wfunc^T + b)
__device__ float g_pre10[BB * DF];          // emb0 @ Wfc1^T + b_fc1
__device__ float g_M[DF * DK];              // W_fc1 @ W_embed
__device__ float g_c1[DF];                  // W_fc1 @ b_embed
__device__ float g_wcomb[NG * DF];          // W_ih @ W_fc2
__device__ float g_gbias[NG];               // W_ih@b_fc2 + b_ih + b_hh
__device__ int   g_thr[BB * NP1];           // first-selected-step per (b,n)
__device__ float g_prefix[BB * TT * DK];    // exclusive prefix of selected keys / N
__device__ float g_relua[BB * TT * DF];     // relu(fc1 pre-activations)
__device__ float g_gx[BB * TT * NG];        // LSTM gate pre-activations
__device__ float g_h[BB * TT * 32];         // LSTM hidden per step

__device__ __forceinline__ float sigmoidf_(float x) {
    return 1.0f / (1.0f + __expf(-x));
}
__device__ __forceinline__ float dot4(float4 a, float4 b) {
    return fmaf(a.x, b.x, fmaf(a.y, b.y, fmaf(a.z, b.z, a.w * b.w)));
}

// pack2(lo, hi): bf16x2 with 'lo' in bits[15:0]
__device__ __forceinline__ uint32_t pack2(float lo, float hi) {
    uint32_t r;
    asm("cvt.rn.bf16x2.f32 %0, %1, %2;" : "=r"(r) : "f"(hi), "f"(lo));
    return r;
}
__device__ __forceinline__ void cvt_hilo(float x0, float x1, uint32_t& h, uint32_t& l) {
    h = pack2(x0, x1);
    float h0 = __uint_as_float(h << 16);
    float h1 = __uint_as_float(h & 0xffff0000u);
    l = pack2(x0 - h0, x1 - h1);
}
__device__ __forceinline__ void mma16816(float* d, uint32_t a0, uint32_t a1,
                                         uint32_t a2, uint32_t a3,
                                         uint32_t b0, uint32_t b1) {
    asm volatile(
        "mma.sync.aligned.m16n8k16.row.col.f32.bf16.bf16.f32 "
        "{%0,%1,%2,%3},{%4,%5,%6,%7},{%8,%9},{%0,%1,%2,%3};"
        : "+f"(d[0]), "+f"(d[1]), "+f"(d[2]), "+f"(d[3])
        : "r"(a0), "r"(a1), "r"(a2), "r"(a3), "r"(b0), "r"(b1));
}

// ================= generic fp32-in / fp32-out GEMM on tensor cores ==========
template <int WARPS_M, int WARPS_N, int BK, bool RELU, bool KEYREMAP>
__global__ void __launch_bounds__(256, 1)
gemm_bf16s(const float* __restrict__ A, const float* __restrict__ Bw,
           float* __restrict__ C, const float* __restrict__ bias,
           int K, int ldc) {
    constexpr int BM = WARPS_M * 16;
    constexpr int BN = WARPS_N * 32;
    constexpr int WPR = BK / 2;
    extern __shared__ uint32_t smem_u[];
    uint32_t* sAh = smem_u;
    uint32_t* sAl = sAh + BM * WPR;
    uint32_t* sBh = sAl + BM * WPR;
    uint32_t* sBl = sBh + BN * WPR;

    const int tid = threadIdx.x;
    const int wid = tid >> 5, lane = tid & 31;
    const int g = lane >> 2, tig = lane & 3;
    const int wm = wid % WARPS_M, wn = wid / WARPS_M;
    const int m0 = blockIdx.x * BM;
    const int n0 = blockIdx.y * BN;
    const bool k4 = ((K & 3) == 0);

    float acc[4][4];
    for (int i = 0; i < 4; i++)
        for (int j = 0; j < 4; j++) acc[i][j] = 0.f;

    const int kiters = (K + BK - 1) / BK;
    for (int kt = 0; kt < kiters; kt++) {
        const int k0 = kt * BK;
        for (int idx = tid; idx < BM * (BK / 4); idx += 256) {
            int row = idx / (BK / 4), c4 = idx % (BK / 4);
            int gc = k0 + c4 * 4;
            float4 v = make_float4(0.f, 0.f, 0.f, 0.f);
            const float* ap = A + (size_t)(m0 + row) * K + gc;
            if (k4 && gc + 4 <= K) {
                v = *(const float4*)ap;
            } else {
                if (gc + 0 < K) v.x = ap[0];
                if (gc + 1 < K) v.y = ap[1];
                if (gc + 2 < K) v.z = ap[2];
                if (gc + 3 < K) v.w = ap[3];
            }
            uint32_t h0, l0, h1, l1;
            cvt_hilo(v.x, v.y, h0, l0);
            cvt_hilo(v.z, v.w, h1, l1);
            int w0 = (c4 * 2) ^ ((row & 7) << 2);
            *(uint2*)&sAh[row * WPR + w0] = make_uint2(h0, h1);
            *(uint2*)&sAl[row * WPR + w0] = make_uint2(l0, l1);
        }
        for (int idx = tid; idx < BN * (BK / 4); idx += 256) {
            int row = idx / (BK / 4), c4 = idx % (BK / 4);
            int gc = k0 + c4 * 4;
            float4 v = make_float4(0.f, 0.f, 0.f, 0.f);
            const float* bp = Bw + (size_t)(n0 + row) * K + gc;
            if (k4 && gc + 4 <= K) {
                v = *(const float4*)bp;
            } else {
                if (gc + 0 < K) v.x = bp[0];
                if (gc + 1 < K) v.y = bp[1];
                if (gc + 2 < K) v.z = bp[2];
                if (gc + 3 < K) v.w = bp[3];
            }
            uint32_t h0, l0, h1, l1;
            cvt_hilo(v.x, v.y, h0, l0);
            cvt_hilo(v.z, v.w, h1, l1);
            int w0 = (c4 * 2) ^ ((row & 7) << 2);
            *(uint2*)&sBh[row * WPR + w0] = make_uint2(h0, h1);
            *(uint2*)&sBl[row * WPR + w0] = make_uint2(l0, l1);
        }
        __syncthreads();
        const int sw = g << 2;
        const int ra0 = (wm * 16 + g) * WPR;
        const int ra1 = (wm * 16 + g + 8) * WPR;
#pragma unroll 4
        for (int c = 0; c < BK / 16; c++) {
            int ws0 = c * 8 + tig;
            uint32_t a0h = sAh[ra0 + (ws0 ^ sw)];
            uint32_t a1h = sAh[ra1 + (ws0 ^ sw)];
            uint32_t a2h = sAh[ra0 + ((ws0 + 4) ^ sw)];
            uint32_t a3h = sAh[ra1 + ((ws0 + 4) ^ sw)];
            uint32_t a0l = sAl[ra0 + (ws0 ^ sw)];
            uint32_t a1l = sAl[ra1 + (ws0 ^ sw)];
            uint32_t a2l = sAl[ra0 + ((ws0 + 4) ^ sw)];
            uint32_t a3l = sAl[ra1 + ((ws0 + 4) ^ sw)];
#pragma unroll
            for (int nt = 0; nt < 4; nt++) {
                int rb = (wn * 32 + nt * 8 + g) * WPR;
                uint32_t b0h = sBh[rb + (ws0 ^ sw)];
                uint32_t b1h = sBh[rb + ((ws0 + 4) ^ sw)];
                uint32_t b0l = sBl[rb + (ws0 ^ sw)];
                uint32_t b1l = sBl[rb + ((ws0 + 4) ^ sw)];
                mma16816(acc[nt], a0h, a1h, a2h, a3h, b0h, b1h);
                mma16816(acc[nt], a0h, a1h, a2h, a3h, b0l, b1l);
                mma16816(acc[nt], a0l, a1l, a2l, a3l, b0h, b1h);
            }
        }
        __syncthreads();
    }
#pragma unroll
    for (int nt = 0; nt < 4; nt++) {
        int col = n0 + wn * 32 + nt * 8 + 2 * tig;
        float b0v = __ldg(&bias[col]);
        float b1v = __ldg(&bias[col + 1]);
#pragma unroll
        for (int half = 0; half < 2; half++) {
            int r = m0 + wm * 16 + g + half * 8;
            int orow = KEYREMAP ? (r + (r >> 9)) : r;
            float x0 = acc[nt][half * 2 + 0] + b0v;
            float x1 = acc[nt][half * 2 + 1] + b1v;
            if (RELU) { x0 = fmaxf(x0, 0.f); x1 = fmaxf(x1, 0.f); }
            *(float2*)&C[(size_t)orow * ldc + col] = make_float2(x0, x1);
        }
    }
}

// ------- M[j,:] = W_fc1[j,:] @ W_embed ; c1[j] = W_fc1[j,:] . b_embed -------
// one block per j; warp w covers i-chunk [w*128,(w+1)*128); lane = output col.
__global__ void k_M2(const float* __restrict__ Wfc1,
                     const float* __restrict__ Wemb,
                     const float* __restrict__ bemb) {
    __shared__ float sred[8 * 32];
    __shared__ float sred1[8];
    int j = blockIdx.x;
    int lane = threadIdx.x & 31, w = threadIdx.x >> 5;
    const float* arow = Wfc1 + (size_t)j * 1024 + w * 128;
    float acc = 0.f;
#pragma unroll 8
    for (int i = 0; i < 128; i++) {
        float a = __ldg(&arow[i]);
        acc = fmaf(a, __ldg(&Wemb[(size_t)(w * 128 + i) * 32 + lane]), acc);
    }
    float a1 = 0.f;
#pragma unroll
    for (int q = 0; q < 4; q++) {
        int i = q * 32 + lane;
        a1 = fmaf(__ldg(&arow[i]), __ldg(&bemb[w * 128 + i]), a1);
    }
#pragma unroll
    for (int off = 16; off > 0; off >>= 1)
        a1 += __shfl_xor_sync(0xffffffffu, a1, off);
    if (lane == 0) sred1[w] = a1;
    sred[w * 32 + lane] = acc;
    __syncthreads();
    if (threadIdx.x < 32) {
        float s = 0.f;
#pragma unroll
        for (int gp = 0; gp < 8; gp++) s += sred[gp * 32 + threadIdx.x];
        g_M[j * 32 + threadIdx.x] = s;
        if (threadIdx.x == 0) {
            float s1 = 0.f;
#pragma unroll
            for (int gp = 0; gp < 8; gp++) s1 += sred1[gp];
            g_c1[j] = s1;
        }
    }
}

// ---------------- Wcomb = W_ih @ W_fc2 ; gbias --------------------------
__global__ void k_wcomb(const float* __restrict__ Wfc2,
                        const float* __restrict__ bfc2,
                        const float* __restrict__ Wih,
                        const float* __restrict__ bih,
                        const float* __restrict__ bhh) {
    __shared__ float sWih[32];
    int gi = blockIdx.x;
    int tid = threadIdx.x;
    if (tid < 32) sWih[tid] = Wih[gi * 32 + tid];
    __syncthreads();
    float acc = 0.f;
#pragma unroll
    for (int k = 0; k < 32; k++) acc = fmaf(sWih[k], __ldg(&Wfc2[k * 256 + tid]), acc);
    g_wcomb[gi * 256 + tid] = acc;
    if (tid == 0) {
        float b = bih[gi] + bhh[gi];
#pragma unroll
        for (int k = 0; k < 32; k++) b = fmaf(sWih[k], bfc2[k], b);
        g_gbias[gi] = b;
    }
}

// -------- availability thresholds + selected-key prefix sums + end rows ----
__global__ void k_prep(const float* __restrict__ avail,
                       const int* __restrict__ selected,
                       const float* __restrict__ endv) {
    __shared__ int s_thr[NP1];
    int b = blockIdx.x;
    int lane = threadIdx.x;  // 32 threads
    g_padkey[((size_t)b * NP1 + 512) * 32 + lane] = endv[lane];
    for (int n = lane; n < NP1; n += 32)
        s_thr[n] = (n == 512) ? 33 : (avail[(size_t)b * 512 + n] > 0.5f ? 33 : -1);
    __syncwarp();
    int selv = selected[b * 32 + lane];
    // batch all 32 selected-row loads (high MLP) — sel < 512 always
    float rr[32];
#pragma unroll
    for (int t = 0; t < 32; t++) {
        int s = __shfl_sync(0xffffffffu, selv, t);
        rr[t] = __ldg(&g_padkey[((size_t)b * NP1 + s) * 32 + lane]);
    }
    float acc = 0.f;
    const float inv_n = 1.0f / 512.0f;
#pragma unroll
    for (int t = 0; t < 32; t++) {
        g_prefix[((size_t)b * TT + t) * 32 + lane] = acc;
        acc = fmaf(rr[t], inv_n, acc);
        int s = __shfl_sync(0xffffffffu, selv, t);
        if (lane == 0) {
            int v = s_thr[s];
            if (v < 0 || v >= 32) s_thr[s] = t;
        }
    }
    __syncwarp();
    g_prefix[((size_t)b * TT + 32) * 32 + lane] = acc;
    for (int n = lane; n < NP1; n += 32)
        g_thr[(size_t)b * NP1 + n] = s_thr[n];
}

// -------- relu_a[b,t,:] = relu(pre10 + func + t*c1 + prefix_t @ M^T) --------
__global__ void k_gA() {
    __shared__ float sp[TT * 32];
    int b = blockIdx.x, tid = threadIdx.x;
    for (int i = tid; i < TT * 32; i += 256) sp[i] = g_prefix[(size_t)b * TT * 32 + i];
    float pre = g_pre10[(size_t)b * 256 + tid] + g_func[(size_t)b * 256 + tid];
    float c1 = g_c1[tid];
    float m[32];
    const float4* mr = reinterpret_cast<const float4*>(g_M + tid * 32);
#pragma unroll
    for (int q = 0; q < 8; q++) {
        float4 v = __ldg(mr + q);
        m[q * 4 + 0] = v.x; m[q * 4 + 1] = v.y; m[q * 4 + 2] = v.z; m[q * 4 + 3] = v.w;
    }
    __syncthreads();
    for (int t = 0; t < TT; t++) {
        float acc = fmaf((float)t, c1, pre);
        const float* p = &sp[t * 32];
#pragma unroll
        for (int k = 0; k < 32; k++) acc = fmaf(m[k], p[k], acc);
        g_relua[((size_t)b * TT + t) * 256 + tid] = fmaxf(acc, 0.f);
    }
}

// ---------------- LSTM recurrence -----------
__global__ void k_lstm(const float* __restrict__ Whh) {
    __shared__ float sW[128 * 33];
    __shared__ float s_h[32];
    __shared__ float s_c[32];
    __shared__ float s_g[128];
    int b = blockIdx.x, tid = threadIdx.x;
    for (int idx = tid; idx < 128 * 32; idx += 128) {
        int gg2 = idx >> 5, kk = idx & 31;
        sW[gg2 * 33 + kk] = Whh[idx];
    }
    if (tid < 32) { s_h[tid] = 0.f; s_c[tid] = 0.f; }
    __syncthreads();
    for (int t = 0; t < TT; t++) {
        float gg = g_gx[((size_t)b * TT + t) * 128 + tid];
        const float* wrow = &sW[tid * 33];
#pragma unroll
        for (int kk = 0; kk < 32; kk++) gg = fmaf(wrow[kk], s_h[kk], gg);
        s_g[tid] = gg;
        __syncthreads();
        if (tid < 32) {
            float ig = sigmoidf_(s_g[tid]);
            float fg = sigmoidf_(s_g[32 + tid]);
            float gt = tanhf(s_g[64 + tid]);
            float og = sigmoidf_(s_g[96 + tid]);
            float c = fmaf(fg, s_c[tid], ig * gt);
            float h = og * tanhf(c);
            s_c[tid] = c;
            s_h[tid] = h;
            g_h[((size_t)b * TT + t) * 32 + tid] = h;
        }
        __syncthreads();
    }
}

// ---------------- logits[b,t,n] = h_t . key_n - mask --------------------
__global__ void k_logits(float* __restrict__ out) {
    __shared__ float s_h[TT * 32];
    __shared__ float s_key[128 * 36];
    int b = blockIdx.y, n0 = blockIdx.x * 128, tid = threadIdx.x;
    for (int idx = tid; idx < TT * 32; idx += 256)
        s_h[idx] = g_h[(size_t)b * (TT * 32) + idx];
    int nmax = NP1 - n0; if (nmax > 128) nmax = 128;
    for (int idx = tid; idx < nmax * 32; idx += 256) {
        int r = idx >> 5, kk = idx & 31;
        s_key[r * 36 + kk] = g_padkey[((size_t)(b * NP1 + n0)) * 32 + idx];
    }
    __syncthreads();
    int nn = tid & 127, ts = tid >> 7;
    if (nn < nmax) {
        int n = n0 + nn;
        float4 kr[8];
        const float4* k4 = reinterpret_cast<const float4*>(&s_key[nn * 36]);
#pragma unroll
        for (int q = 0; q < 8; q++) kr[q] = k4[q];
        int thr = g_thr[(size_t)b * NP1 + n];
        for (int t = ts; t < TT; t += 2) {
            const float4* h4 = reinterpret_cast<const float4*>(&s_h[t * 32]);
            float acc = 0.f;
#pragma unroll
            for (int q = 0; q < 8; q++) acc += dot4(h4[q], kr[q]);
            out[((size_t)b * TT + t) * NP1 + n] = acc - (t > thr ? 1e9f : 0.f);
        }
    }
}

// ---------------- final emb output ---------------------------------------
__global__ void k_emb(float* __restrict__ out,
                      const float* __restrict__ emb0,
                      const float* __restrict__ Wemb,
                      const float* __restrict__ bemb) {
    __shared__ float s_p[32];
    int b = blockIdx.x, tid = threadIdx.x;
    if (tid < 32) s_p[tid] = g_prefix[((size_t)b * TT + 32) * 32 + tid];
    __syncthreads();
    const float4* p4 = reinterpret_cast<const float4*>(s_p);
#pragma unroll
    for (int q = 0; q < 4; q++) {
        int i = q * 256 + tid;
        const float4* we = reinterpret_cast<const float4*>(Wemb + (size_t)i * 32);
        float acc = __ldg(&emb0[(size_t)b * 1024 + i]) + 32.0f * __ldg(&bemb[i]);
#pragma unroll
        for (int r = 0; r < 8; r++) acc += dot4(__ldg(we + r), p4[r]);
        out[LOGITS_ELEMS + (size_t)b * 1024 + i] = acc;
    }
}

// ---------------- launch -----------------------------------------------------
extern "C" void kernel_launch(void* const* d_in, const int* in_sizes, int n_in,
                              void* d_out, int out_size) {
    const float* embedding = (const float*)d_in[0];
    const float* type_mask = (const float*)d_in[1];
    const float* avail     = (const float*)d_in[2];
    const float* ent       = (const float*)d_in[3];
    const int*   selected  = (const int*)d_in[4];
    const float* endv      = (const float*)d_in[5];
    const float* W_key  = (const float*)d_in[6];
    const float* b_key  = (const float*)d_in[7];
    const float* W_func = (const float*)d_in[8];
    const float* b_func = (const float*)d_in[9];
    const float* W_fc1  = (const float*)d_in[10];
    const float* b_fc1  = (const float*)d_in[11];
    const float* W_fc2  = (const float*)d_in[12];
    const float* b_fc2  = (const float*)d_in[13];
    const float* W_emb  = (const float*)d_in[14];
    const float* b_emb  = (const float*)d_in[15];
    const float* W_ih   = (const float*)d_in[16];
    const float* b_ih   = (const float*)d_in[17];
    const float* W_hh   = (const float*)d_in[18];
    const float* b_hh   = (const float*)d_in[19];
    float* out = (float*)d_out;

    const int SM1 = 163840, SM2 = 65536;
    cudaFuncSetAttribute(gemm_bf16s<8, 1, 256, false, true>,
                         cudaFuncAttributeMaxDynamicSharedMemorySize, SM1);
    cudaFuncSetAttribute(gemm_bf16s<8, 1, 256, false, false>,
                         cudaFuncAttributeMaxDynamicSharedMemorySize, SM1);
    cudaFuncSetAttribute(gemm_bf16s<4, 2, 128, false, false>,
                         cudaFuncAttributeMaxDynamicSharedMemorySize, SM2);
    cudaFuncSetAttribute(gemm_bf16s<4, 2, 128, true, false>,
                         cudaFuncAttributeMaxDynamicSharedMemorySize, SM2);

    float* padkey; cudaGetSymbolAddress((void**)&padkey, g_padkey);
    float* pre10;  cudaGetSymbolAddress((void**)&pre10, g_pre10);
    float* funcb;  cudaGetSymbolAddress((void**)&funcb, g_func);
    float* relua;  cudaGetSymbolAddress((void**)&relua, g_relua);
    float* wcomb;  cudaGetSymbolAddress((void**)&wcomb, g_wcomb);
    float* gbias;  cudaGetSymbolAddress((void**)&gbias, g_gbias);
    float* gx;     cudaGetSymbolAddress((void**)&gx, g_gx);

    // Side stream + events (created per call; never destroyed — destroying a
    // capture-participating stream/event mid-capture would invalidate capture.
    // kernel_launch runs only a handful of times, so the leak is bounded.)
    cudaStream_t s1;
    cudaStreamCreateWithFlags(&s1, cudaStreamNonBlocking);
    cudaEvent_t evFork, evS1, evPrep, evEmb;
    cudaEventCreateWithFlags(&evFork, cudaEventDisableTiming);
    cudaEventCreateWithFlags(&evS1, cudaEventDisableTiming);
    cudaEventCreateWithFlags(&evPrep, cudaEventDisableTiming);
    cudaEventCreateWithFlags(&evEmb, cudaEventDisableTiming);

    // ---- fork: side branch (independent of the big key GEMM) ----
    cudaEventRecord(evFork, 0);
    cudaStreamWaitEvent(s1, evFork, 0);
    gemm_bf16s<4, 2, 128, false, false>
        <<<dim3(4, 4), 256, SM2, s1>>>(embedding, W_fc1, pre10, b_fc1, 1024, 256);
    gemm_bf16s<4, 2, 128, true, false>
        <<<dim3(4, 4), 256, SM2, s1>>>(type_mask, W_func, funcb, b_func, DTY, 256);
    k_M2<<<256, 256, 0, s1>>>(W_fc1, W_emb, b_emb);
    k_wcomb<<<128, 256, 0, s1>>>(W_fc2, b_fc2, W_ih, b_ih, b_hh);
    cudaEventRecord(evS1, s1);

    // ---- main stream: key GEMM -> prep ----
    gemm_bf16s<8, 1, 256, false, true>
        <<<dim3(BB * NN / 128, 1), 256, SM1>>>(ent, W_key, padkey, b_key, 256, 32);
    k_prep<<<BB, 32>>>(avail, selected, endv);
    cudaEventRecord(evPrep, 0);

    // ---- k_emb only needs g_prefix: run on side stream ----
    cudaStreamWaitEvent(s1, evPrep, 0);
    k_emb<<<BB, 256, 0, s1>>>(out, embedding, W_emb, b_emb);
    cudaEventRecord(evEmb, s1);

    // ---- main chain continues after side precomputes land ----
    cudaStreamWaitEvent(0, evS1, 0);
    k_gA<<<BB, 256>>>();
    gemm_bf16s<8, 1, 256, false, false>
        <<<dim3(BB * TT / 128, 4), 256, SM1>>>(relua, wcomb, gx, gbias, 256, 128);
    k_lstm<<<BB, 128>>>(W_hh);
    k_logits<<<dim3(5, BB), 256>>>(out);

    // ---- join ----
    cudaStreamWaitEvent(0, evEmb, 0);
}

// round 11
// speedup vs baseline: 3.4374x; 1.3994x over previous
#include <cuda_runtime.h>
#include <cuda_bf16.h>
#include <cstdint>

#define BB 256
#define NN 512
#define NP1 513
#define TT 33
#define DK 32
#define DIN 1024
#define DF 256
#define DTY 259
#define NG 128

#define LOGITS_ELEMS ((size_t)BB * TT * NP1)

// ---------------- scratch (device globals; no allocation allowed) ----------
__device__ float g_padkey[BB * NP1 * DK];   // keys + end row
__device__ float g_func[BB * DF];           // relu(mask_type @ Wfunc^T + b)
__device__ float g_pre10[BB * DF];          // emb0 @ Wfc1^T + b_fc1
__device__ float g_M[DF * DK];              // W_fc1 @ W_embed
__device__ float g_c1[DF];                  // W_fc1 @ b_embed
__device__ float g_wcomb[NG * DF];          // W_ih @ W_fc2
__device__ float g_gbias[NG];               // W_ih@b_fc2 + b_ih + b_hh
__device__ int   g_thr[BB * NP1];           // first-selected-step per (b,n)
__device__ float g_prefix[BB * TT * DK];    // exclusive prefix of selected keys / N
__device__ float g_relua[BB * TT * DF];     // relu(fc1 pre-activations)
__device__ float g_gx[BB * TT * NG];        // LSTM gate pre-activations
__device__ float g_h[BB * TT * 32];         // LSTM hidden per step

__device__ __forceinline__ float sigmoidf_(float x) {
    return 1.0f / (1.0f + __expf(-x));
}
__device__ __forceinline__ float dot4(float4 a, float4 b) {
    return fmaf(a.x, b.x, fmaf(a.y, b.y, fmaf(a.z, b.z, a.w * b.w)));
}

// pack2(lo, hi): bf16x2 with 'lo' in bits[15:0]
__device__ __forceinline__ uint32_t pack2(float lo, float hi) {
    uint32_t r;
    asm("cvt.rn.bf16x2.f32 %0, %1, %2;" : "=r"(r) : "f"(hi), "f"(lo));
    return r;
}
__device__ __forceinline__ void cvt_hilo(float x0, float x1, uint32_t& h, uint32_t& l) {
    h = pack2(x0, x1);
    float h0 = __uint_as_float(h << 16);
    float h1 = __uint_as_float(h & 0xffff0000u);
    l = pack2(x0 - h0, x1 - h1);
}
__device__ __forceinline__ void mma16816(float* d, uint32_t a0, uint32_t a1,
                                         uint32_t a2, uint32_t a3,
                                         uint32_t b0, uint32_t b1) {
    asm volatile(
        "mma.sync.aligned.m16n8k16.row.col.f32.bf16.bf16.f32 "
        "{%0,%1,%2,%3},{%4,%5,%6,%7},{%8,%9},{%0,%1,%2,%3};"
        : "+f"(d[0]), "+f"(d[1]), "+f"(d[2]), "+f"(d[3])
        : "r"(a0), "r"(a1), "r"(a2), "r"(a3), "r"(b0), "r"(b1));
}

// ================= generic fp32-in / fp32-out GEMM body (tensor cores) ======
// C[m,n] = sum_k A[m,k]*Bw[n,k] + bias[n]; optional relu; optional key remap.
template <int WARPS_M, int WARPS_N, int BK, bool KEYREMAP>
__device__ __forceinline__ void
gemm_body(const float* __restrict__ A, const float* __restrict__ Bw,
          float* __restrict__ C, const float* __restrict__ bias,
          int K, int ldc, bool relu, int m0, int n0) {
    constexpr int BM = WARPS_M * 16;
    constexpr int BN = WARPS_N * 32;
    constexpr int WPR = BK / 2;
    extern __shared__ uint32_t smem_u[];
    uint32_t* sAh = smem_u;
    uint32_t* sAl = sAh + BM * WPR;
    uint32_t* sBh = sAl + BM * WPR;
    uint32_t* sBl = sBh + BN * WPR;

    const int tid = threadIdx.x;
    const int wid = tid >> 5, lane = tid & 31;
    const int g = lane >> 2, tig = lane & 3;
    const int wm = wid % WARPS_M, wn = wid / WARPS_M;
    const bool k4 = ((K & 3) == 0);
    constexpr int NT = 256;

    float acc[4][4];
    for (int i = 0; i < 4; i++)
        for (int j = 0; j < 4; j++) acc[i][j] = 0.f;

    const int kiters = (K + BK - 1) / BK;
    for (int kt = 0; kt < kiters; kt++) {
        const int k0 = kt * BK;
        for (int idx = tid; idx < BM * (BK / 4); idx += NT) {
            int row = idx / (BK / 4), c4 = idx % (BK / 4);
            int gc = k0 + c4 * 4;
            float4 v = make_float4(0.f, 0.f, 0.f, 0.f);
            const float* ap = A + (size_t)(m0 + row) * K + gc;
            if (k4 && gc + 4 <= K) {
                v = *(const float4*)ap;
            } else {
                if (gc + 0 < K) v.x = ap[0];
                if (gc + 1 < K) v.y = ap[1];
                if (gc + 2 < K) v.z = ap[2];
                if (gc + 3 < K) v.w = ap[3];
            }
            uint32_t h0, l0, h1, l1;
            cvt_hilo(v.x, v.y, h0, l0);
            cvt_hilo(v.z, v.w, h1, l1);
            int w0 = (c4 * 2) ^ ((row & 7) << 2);
            *(uint2*)&sAh[row * WPR + w0] = make_uint2(h0, h1);
            *(uint2*)&sAl[row * WPR + w0] = make_uint2(l0, l1);
        }
        for (int idx = tid; idx < BN * (BK / 4); idx += NT) {
            int row = idx / (BK / 4), c4 = idx % (BK / 4);
            int gc = k0 + c4 * 4;
            float4 v = make_float4(0.f, 0.f, 0.f, 0.f);
            const float* bp = Bw + (size_t)(n0 + row) * K + gc;
            if (k4 && gc + 4 <= K) {
                v = *(const float4*)bp;
            } else {
                if (gc + 0 < K) v.x = bp[0];
                if (gc + 1 < K) v.y = bp[1];
                if (gc + 2 < K) v.z = bp[2];
                if (gc + 3 < K) v.w = bp[3];
            }
            uint32_t h0, l0, h1, l1;
            cvt_hilo(v.x, v.y, h0, l0);
            cvt_hilo(v.z, v.w, h1, l1);
            int w0 = (c4 * 2) ^ ((row & 7) << 2);
            *(uint2*)&sBh[row * WPR + w0] = make_uint2(h0, h1);
            *(uint2*)&sBl[row * WPR + w0] = make_uint2(l0, l1);
        }
        __syncthreads();
        const int sw = g << 2;
        const int ra0 = (wm * 16 + g) * WPR;
        const int ra1 = (wm * 16 + g + 8) * WPR;
#pragma unroll 4
        for (int c = 0; c < BK / 16; c++) {
            int ws0 = c * 8 + tig;
            uint32_t a0h = sAh[ra0 + (ws0 ^ sw)];
            uint32_t a1h = sAh[ra1 + (ws0 ^ sw)];
            uint32_t a2h = sAh[ra0 + ((ws0 + 4) ^ sw)];
            uint32_t a3h = sAh[ra1 + ((ws0 + 4) ^ sw)];
            uint32_t a0l = sAl[ra0 + (ws0 ^ sw)];
            uint32_t a1l = sAl[ra1 + (ws0 ^ sw)];
            uint32_t a2l = sAl[ra0 + ((ws0 + 4) ^ sw)];
            uint32_t a3l = sAl[ra1 + ((ws0 + 4) ^ sw)];
#pragma unroll
            for (int nt = 0; nt < 4; nt++) {
                int rb = (wn * 32 + nt * 8 + g) * WPR;
                uint32_t b0h = sBh[rb + (ws0 ^ sw)];
                uint32_t b1h = sBh[rb + ((ws0 + 4) ^ sw)];
                uint32_t b0l = sBl[rb + (ws0 ^ sw)];
                uint32_t b1l = sBl[rb + ((ws0 + 4) ^ sw)];
                mma16816(acc[nt], a0h, a1h, a2h, a3h, b0h, b1h);
                mma16816(acc[nt], a0h, a1h, a2h, a3h, b0l, b1l);
                mma16816(acc[nt], a0l, a1l, a2l, a3l, b0h, b1h);
            }
        }
        __syncthreads();
    }
#pragma unroll
    for (int nt = 0; nt < 4; nt++) {
        int col = n0 + wn * 32 + nt * 8 + 2 * tig;
        float b0v = __ldg(&bias[col]);
        float b1v = __ldg(&bias[col + 1]);
#pragma unroll
        for (int half = 0; half < 2; half++) {
            int r = m0 + wm * 16 + g + half * 8;
            int orow = KEYREMAP ? (r + (r >> 9)) : r;
            float x0 = acc[nt][half * 2 + 0] + b0v;
            float x1 = acc[nt][half * 2 + 1] + b1v;
            if (relu) { x0 = fmaxf(x0, 0.f); x1 = fmaxf(x1, 0.f); }
            *(float2*)&C[(size_t)orow * ldc + col] = make_float2(x0, x1);
        }
    }
}

// key GEMM wrapper: BK=128 -> 80KB smem -> 2 CTAs/SM
template <int WARPS_M, int WARPS_N, int BK, bool KEYREMAP>
__global__ void __launch_bounds__(256, 2)
gemm_k(const float* __restrict__ A, const float* __restrict__ Bw,
       float* __restrict__ C, const float* __restrict__ bias, int K, int ldc) {
    gemm_body<WARPS_M, WARPS_N, BK, KEYREMAP>(
        A, Bw, C, bias, K, ldc, false,
        blockIdx.x * WARPS_M * 16, blockIdx.y * WARPS_N * 32);
}
// gates GEMM wrapper (same config, no remap)
template <int WARPS_M, int WARPS_N, int BK>
__global__ void __launch_bounds__(256, 2)
gemm_g(const float* __restrict__ A, const float* __restrict__ Bw,
       float* __restrict__ C, const float* __restrict__ bias, int K, int ldc) {
    gemm_body<WARPS_M, WARPS_N, BK, false>(
        A, Bw, C, bias, K, ldc, false,
        blockIdx.x * WARPS_M * 16, blockIdx.y * WARPS_N * 32);
}
// dual small GEMM: z=0 -> pre10 (K=1024), z=1 -> func (K=259, relu)
__global__ void __launch_bounds__(256, 2)
gemm_dual(const float* A0, const float* B0, float* C0, const float* bias0, int K0,
          const float* A1, const float* B1, float* C1, const float* bias1, int K1) {
    if (blockIdx.z == 0)
        gemm_body<4, 2, 128, false>(A0, B0, C0, bias0, K0, 256, false,
                                    blockIdx.x * 64, blockIdx.y * 64);
    else
        gemm_body<4, 2, 128, false>(A1, B1, C1, bias1, K1, 256, true,
                                    blockIdx.x * 64, blockIdx.y * 64);
}

// ------- merged side precomputes: blocks 0..255 -> M/c1 row j; 256..383 -> wcomb
__global__ void k_side(const float* __restrict__ Wfc1,
                       const float* __restrict__ Wemb,
                       const float* __restrict__ bemb,
                       const float* __restrict__ Wfc2,
                       const float* __restrict__ bfc2,
                       const float* __restrict__ Wih,
                       const float* __restrict__ bih,
                       const float* __restrict__ bhh) {
    if (blockIdx.x < 256) {
        __shared__ float sred[8 * 32];
        __shared__ float sred1[8];
        int j = blockIdx.x;
        int lane = threadIdx.x & 31, w = threadIdx.x >> 5;
        const float* arow = Wfc1 + (size_t)j * 1024 + w * 128;
        float acc = 0.f;
#pragma unroll 8
        for (int i = 0; i < 128; i++) {
            float a = __ldg(&arow[i]);
            acc = fmaf(a, __ldg(&Wemb[(size_t)(w * 128 + i) * 32 + lane]), acc);
        }
        float a1 = 0.f;
#pragma unroll
        for (int q = 0; q < 4; q++) {
            int i = q * 32 + lane;
            a1 = fmaf(__ldg(&arow[i]), __ldg(&bemb[w * 128 + i]), a1);
        }
#pragma unroll
        for (int off = 16; off > 0; off >>= 1)
            a1 += __shfl_xor_sync(0xffffffffu, a1, off);
        if (lane == 0) sred1[w] = a1;
        sred[w * 32 + lane] = acc;
        __syncthreads();
        if (threadIdx.x < 32) {
            float s = 0.f;
#pragma unroll
            for (int gp = 0; gp < 8; gp++) s += sred[gp * 32 + threadIdx.x];
            g_M[j * 32 + threadIdx.x] = s;
            if (threadIdx.x == 0) {
                float s1 = 0.f;
#pragma unroll
                for (int gp = 0; gp < 8; gp++) s1 += sred1[gp];
                g_c1[j] = s1;
            }
        }
    } else {
        __shared__ float sWih[32];
        int gi = blockIdx.x - 256;
        int tid = threadIdx.x;
        if (tid < 32) sWih[tid] = Wih[gi * 32 + tid];
        __syncthreads();
        float acc = 0.f;
#pragma unroll
        for (int k = 0; k < 32; k++)
            acc = fmaf(sWih[k], __ldg(&Wfc2[k * 256 + tid]), acc);
        g_wcomb[gi * 256 + tid] = acc;
        if (tid == 0) {
            float b = bih[gi] + bhh[gi];
#pragma unroll
            for (int k = 0; k < 32; k++) b = fmaf(sWih[k], bfc2[k], b);
            g_gbias[gi] = b;
        }
    }
}

// -------- availability thresholds + selected-key prefix sums + end rows ----
__global__ void k_prep(const float* __restrict__ avail,
                       const int* __restrict__ selected,
                       const float* __restrict__ endv) {
    __shared__ int s_thr[NP1];
    int b = blockIdx.x;
    int lane = threadIdx.x;  // 32 threads
    g_padkey[((size_t)b * NP1 + 512) * 32 + lane] = endv[lane];
    for (int n = lane; n < NP1; n += 32)
        s_thr[n] = (n == 512) ? 33 : (avail[(size_t)b * 512 + n] > 0.5f ? 33 : -1);
    __syncwarp();
    int selv = selected[b * 32 + lane];
    float rr[32];
#pragma unroll
    for (int t = 0; t < 32; t++) {
        int s = __shfl_sync(0xffffffffu, selv, t);
        rr[t] = __ldg(&g_padkey[((size_t)b * NP1 + s) * 32 + lane]);
    }
    float acc = 0.f;
    const float inv_n = 1.0f / 512.0f;
#pragma unroll
    for (int t = 0; t < 32; t++) {
        g_prefix[((size_t)b * TT + t) * 32 + lane] = acc;
        acc = fmaf(rr[t], inv_n, acc);
        int s = __shfl_sync(0xffffffffu, selv, t);
        if (lane == 0) {
            int v = s_thr[s];
            if (v < 0 || v >= 32) s_thr[s] = t;
        }
    }
    __syncwarp();
    g_prefix[((size_t)b * TT + 32) * 32 + lane] = acc;
    for (int n = lane; n < NP1; n += 32)
        g_thr[(size_t)b * NP1 + n] = s_thr[n];
}

// -------- relu_a[b,t,:] = relu(pre10 + func + t*c1 + prefix_t @ M^T) --------
__global__ void k_gA() {
    __shared__ float sp[TT * 32];
    int b = blockIdx.x, tid = threadIdx.x;
    for (int i = tid; i < TT * 32; i += 256) sp[i] = g_prefix[(size_t)b * TT * 32 + i];
    float pre = g_pre10[(size_t)b * 256 + tid] + g_func[(size_t)b * 256 + tid];
    float c1 = g_c1[tid];
    float m[32];
    const float4* mr = reinterpret_cast<const float4*>(g_M + tid * 32);
#pragma unroll
    for (int q = 0; q < 8; q++) {
        float4 v = __ldg(mr + q);
        m[q * 4 + 0] = v.x; m[q * 4 + 1] = v.y; m[q * 4 + 2] = v.z; m[q * 4 + 3] = v.w;
    }
    __syncthreads();
    for (int t = 0; t < TT; t++) {
        float acc = fmaf((float)t, c1, pre);
        const float* p = &sp[t * 32];
#pragma unroll
        for (int k = 0; k < 32; k++) acc = fmaf(m[k], p[k], acc);
        g_relua[((size_t)b * TT + t) * 256 + tid] = fmaxf(acc, 0.f);
    }
}

// ---------------- LSTM recurrence -----------
__global__ void k_lstm(const float* __restrict__ Whh) {
    __shared__ float sW[128 * 33];
    __shared__ float s_h[32];
    __shared__ float s_c[32];
    __shared__ float s_g[128];
    int b = blockIdx.x, tid = threadIdx.x;
    for (int idx = tid; idx < 128 * 32; idx += 128) {
        int gg2 = idx >> 5, kk = idx & 31;
        sW[gg2 * 33 + kk] = Whh[idx];
    }
    if (tid < 32) { s_h[tid] = 0.f; s_c[tid] = 0.f; }
    __syncthreads();
    for (int t = 0; t < TT; t++) {
        float gg = g_gx[((size_t)b * TT + t) * 128 + tid];
        const float* wrow = &sW[tid * 33];
#pragma unroll
        for (int kk = 0; kk < 32; kk++) gg = fmaf(wrow[kk], s_h[kk], gg);
        s_g[tid] = gg;
        __syncthreads();
        if (tid < 32) {
            float ig = sigmoidf_(s_g[tid]);
            float fg = sigmoidf_(s_g[32 + tid]);
            float gt = tanhf(s_g[64 + tid]);
            float og = sigmoidf_(s_g[96 + tid]);
            float c = fmaf(fg, s_c[tid], ig * gt);
            float h = og * tanhf(c);
            s_c[tid] = c;
            s_h[tid] = h;
            g_h[((size_t)b * TT + t) * 32 + tid] = h;
        }
        __syncthreads();
    }
}

// ---------------- logits[b,t,n] = h_t . key_n - mask --------------------
__global__ void k_logits(float* __restrict__ out) {
    __shared__ float s_h[TT * 32];
    __shared__ float s_key[128 * 36];
    int b = blockIdx.y, n0 = blockIdx.x * 128, tid = threadIdx.x;
    for (int idx = tid; idx < TT * 32; idx += 256)
        s_h[idx] = g_h[(size_t)b * (TT * 32) + idx];
    int nmax = NP1 - n0; if (nmax > 128) nmax = 128;
    for (int idx = tid; idx < nmax * 32; idx += 256) {
        int r = idx >> 5, kk = idx & 31;
        s_key[r * 36 + kk] = g_padkey[((size_t)(b * NP1 + n0)) * 32 + idx];
    }
    __syncthreads();
    int nn = tid & 127, ts = tid >> 7;
    if (nn < nmax) {
        int n = n0 + nn;
        float4 kr[8];
        const float4* k4 = reinterpret_cast<const float4*>(&s_key[nn * 36]);
#pragma unroll
        for (int q = 0; q < 8; q++) kr[q] = k4[q];
        int thr = g_thr[(size_t)b * NP1 + n];
        for (int t = ts; t < TT; t += 2) {
            const float4* h4 = reinterpret_cast<const float4*>(&s_h[t * 32]);
            float acc = 0.f;
#pragma unroll
            for (int q = 0; q < 8; q++) acc += dot4(h4[q], kr[q]);
            out[((size_t)b * TT + t) * NP1 + n] = acc - (t > thr ? 1e9f : 0.f);
        }
    }
}

// ---------------- final emb output ---------------------------------------
__global__ void k_emb(float* __restrict__ out,
                      const float* __restrict__ emb0,
                      const float* __restrict__ Wemb,
                      const float* __restrict__ bemb) {
    __shared__ float s_p[32];
    int b = blockIdx.x, tid = threadIdx.x;
    if (tid < 32) s_p[tid] = g_prefix[((size_t)b * TT + 32) * 32 + tid];
    __syncthreads();
    const float4* p4 = reinterpret_cast<const float4*>(s_p);
#pragma unroll
    for (int q = 0; q < 4; q++) {
        int i = q * 256 + tid;
        const float4* we = reinterpret_cast<const float4*>(Wemb + (size_t)i * 32);
        float acc = __ldg(&emb0[(size_t)b * 1024 + i]) + 32.0f * __ldg(&bemb[i]);
#pragma unroll
        for (int r = 0; r < 8; r++) acc += dot4(__ldg(we + r), p4[r]);
        out[LOGITS_ELEMS + (size_t)b * 1024 + i] = acc;
    }
}

// ---------------- launch -----------------------------------------------------
extern "C" void kernel_launch(void* const* d_in, const int* in_sizes, int n_in,
                              void* d_out, int out_size) {
    const float* embedding = (const float*)d_in[0];
    const float* type_mask = (const float*)d_in[1];
    const float* avail     = (const float*)d_in[2];
    const float* ent       = (const float*)d_in[3];
    const int*   selected  = (const int*)d_in[4];
    const float* endv      = (const float*)d_in[5];
    const float* W_key  = (const float*)d_in[6];
    const float* b_key  = (const float*)d_in[7];
    const float* W_func = (const float*)d_in[8];
    const float* b_func = (const float*)d_in[9];
    const float* W_fc1  = (const float*)d_in[10];
    const float* b_fc1  = (const float*)d_in[11];
    const float* W_fc2  = (const float*)d_in[12];
    const float* b_fc2  = (const float*)d_in[13];
    const float* W_emb  = (const float*)d_in[14];
    const float* b_emb  = (const float*)d_in[15];
    const float* W_ih   = (const float*)d_in[16];
    const float* b_ih   = (const float*)d_in[17];
    const float* W_hh   = (const float*)d_in[18];
    const float* b_hh   = (const float*)d_in[19];
    float* out = (float*)d_out;

    // smem: (8,1,128): 2*(128+32)*64*4 = 81920 B -> 2 CTAs/SM
    //       (4,2,128): 2*(64+64)*64*4  = 65536 B
    const int SMB = 81920, SM2 = 65536;
    cudaFuncSetAttribute(gemm_k<8, 1, 128, true>,
                         cudaFuncAttributeMaxDynamicSharedMemorySize, SMB);
    cudaFuncSetAttribute(gemm_g<8, 1, 128>,
                         cudaFuncAttributeMaxDynamicSharedMemorySize, SMB);
    cudaFuncSetAttribute(gemm_dual,
                         cudaFuncAttributeMaxDynamicSharedMemorySize, SM2);

    float* padkey; cudaGetSymbolAddress((void**)&padkey, g_padkey);
    float* pre10;  cudaGetSymbolAddress((void**)&pre10, g_pre10);
    float* funcb;  cudaGetSymbolAddress((void**)&funcb, g_func);
    float* relua;  cudaGetSymbolAddress((void**)&relua, g_relua);
    float* gx;     cudaGetSymbolAddress((void**)&gx, g_gx);
    float* wcomb;  cudaGetSymbolAddress((void**)&wcomb, g_wcomb);
    float* gbias;  cudaGetSymbolAddress((void**)&gbias, g_gbias);

    cudaStream_t s1;
    cudaStreamCreateWithFlags(&s1, cudaStreamNonBlocking);
    cudaEvent_t evFork, evS1, evPrep, evEmb;
    cudaEventCreateWithFlags(&evFork, cudaEventDisableTiming);
    cudaEventCreateWithFlags(&evS1, cudaEventDisableTiming);
    cudaEventCreateWithFlags(&evPrep, cudaEventDisableTiming);
    cudaEventCreateWithFlags(&evEmb, cudaEventDisableTiming);

    // ---- fork: side branch (independent of the big key GEMM) ----
    cudaEventRecord(evFork, 0);
    cudaStreamWaitEvent(s1, evFork, 0);
    gemm_dual<<<dim3(4, 4, 2), 256, SM2, s1>>>(
        embedding, W_fc1, pre10, b_fc1, 1024,
        type_mask, W_func, funcb, b_func, DTY);
    k_side<<<384, 256, 0, s1>>>(W_fc1, W_emb, b_emb, W_fc2, b_fc2, W_ih, b_ih, b_hh);
    cudaEventRecord(evS1, s1);

    // ---- main stream: key GEMM -> prep ----
    gemm_k<8, 1, 128, true>
        <<<dim3(BB * NN / 128, 1), 256, SMB>>>(ent, W_key, padkey, b_key, 256, 32);
    k_prep<<<BB, 32>>>(avail, selected, endv);
    cudaEventRecord(evPrep, 0);

    // ---- k_emb only needs g_prefix: run on side stream ----
    cudaStreamWaitEvent(s1, evPrep, 0);
    k_emb<<<BB, 256, 0, s1>>>(out, embedding, W_emb, b_emb);
    cudaEventRecord(evEmb, s1);

    // ---- main chain continues after side precomputes land ----
    cudaStreamWaitEvent(0, evS1, 0);
    k_gA<<<BB, 256>>>();
    gemm_g<8, 1, 128>
        <<<dim3(BB * TT / 128, 4), 256, SMB>>>(relua, wcomb, gx, gbias, 256, 128);
    k_lstm<<<BB, 128>>>(W_hh);
    k_logits<<<dim3(5, BB), 256>>>(out);

    // ---- join ----
    cudaStreamWaitEvent(0, evEmb, 0);
}

// round 14
// speedup vs baseline: 3.4576x; 1.0059x over previous
#include <cuda_runtime.h>
#include <cuda_bf16.h>
#include <cstdint>

#define BB 256
#define NN 512
#define NP1 513
#define TT 33
#define DK 32
#define DIN 1024
#define DF 256
#define DTY 259
#define NG 128

#define LOGITS_ELEMS ((size_t)BB * TT * NP1)

// ---------------- scratch (device globals; no allocation allowed) ----------
__device__ float g_padkey[BB * NP1 * DK];   // keys + end row
__device__ float g_func[BB * DF];           // relu(mask_type @ Wfunc^T + b)
__device__ float g_pre10[BB * DF];          // emb0 @ Wfc1^T + b_fc1
__device__ float g_M[DF * DK];              // W_fc1 @ W_embed
__device__ float g_c1[DF];                  // W_fc1 @ b_embed
__device__ float g_wcomb[NG * DF];          // W_ih @ W_fc2
__device__ float g_gbias[NG];               // W_ih@b_fc2 + b_ih + b_hh
__device__ int   g_thr[BB * NP1];           // first-selected-step per (b,n)
__device__ float g_prefix[BB * TT * DK];    // exclusive prefix of selected keys / N
__device__ float g_relua[BB * TT * DF];     // relu(fc1 pre-activations)
__device__ float g_gx[BB * TT * NG];        // LSTM gate pre-activations
__device__ float g_h[BB * TT * 32];         // LSTM hidden per step

__device__ __forceinline__ float sigmoidf_(float x) {
    return 1.0f / (1.0f + __expf(-x));
}
__device__ __forceinline__ float dot4(float4 a, float4 b) {
    return fmaf(a.x, b.x, fmaf(a.y, b.y, fmaf(a.z, b.z, a.w * b.w)));
}

// pack2(lo, hi): bf16x2 with 'lo' in bits[15:0]
__device__ __forceinline__ uint32_t pack2(float lo, float hi) {
    uint32_t r;
    asm("cvt.rn.bf16x2.f32 %0, %1, %2;" : "=r"(r) : "f"(hi), "f"(lo));
    return r;
}
__device__ __forceinline__ void cvt_hilo(float x0, float x1, uint32_t& h, uint32_t& l) {
    h = pack2(x0, x1);
    float h0 = __uint_as_float(h << 16);
    float h1 = __uint_as_float(h & 0xffff0000u);
    l = pack2(x0 - h0, x1 - h1);
}
__device__ __forceinline__ void mma16816(float* d, uint32_t a0, uint32_t a1,
                                         uint32_t a2, uint32_t a3,
                                         uint32_t b0, uint32_t b1) {
    asm volatile(
        "mma.sync.aligned.m16n8k16.row.col.f32.bf16.bf16.f32 "
        "{%0,%1,%2,%3},{%4,%5,%6,%7},{%8,%9},{%0,%1,%2,%3};"
        : "+f"(d[0]), "+f"(d[1]), "+f"(d[2]), "+f"(d[3])
        : "r"(a0), "r"(a1), "r"(a2), "r"(a3), "r"(b0), "r"(b1));
}

// ================= generic fp32-in / fp32-out GEMM body (tensor cores) ======
// C[m,n] = sum_k A[m,k]*Bw[n,k] + bias[n]; optional relu; optional key remap.
template <int WARPS_M, int WARPS_N, int BK, bool KEYREMAP>
__device__ __forceinline__ void
gemm_body(const float* __restrict__ A, const float* __restrict__ Bw,
          float* __restrict__ C, const float* __restrict__ bias,
          int K, int ldc, bool relu, int m0, int n0) {
    constexpr int BM = WARPS_M * 16;
    constexpr int BN = WARPS_N * 32;
    constexpr int WPR = BK / 2;
    extern __shared__ uint32_t smem_u[];
    uint32_t* sAh = smem_u;
    uint32_t* sAl = sAh + BM * WPR;
    uint32_t* sBh = sAl + BM * WPR;
    uint32_t* sBl = sBh + BN * WPR;

    const int tid = threadIdx.x;
    const int wid = tid >> 5, lane = tid & 31;
    const int g = lane >> 2, tig = lane & 3;
    const int wm = wid % WARPS_M, wn = wid / WARPS_M;
    const bool k4 = ((K & 3) == 0);
    constexpr int NT = 256;

    float acc[4][4];
    for (int i = 0; i < 4; i++)
        for (int j = 0; j < 4; j++) acc[i][j] = 0.f;

    const int kiters = (K + BK - 1) / BK;
    for (int kt = 0; kt < kiters; kt++) {
        const int k0 = kt * BK;
        for (int idx = tid; idx < BM * (BK / 4); idx += NT) {
            int row = idx / (BK / 4), c4 = idx % (BK / 4);
            int gc = k0 + c4 * 4;
            float4 v = make_float4(0.f, 0.f, 0.f, 0.f);
            const float* ap = A + (size_t)(m0 + row) * K + gc;
            if (k4 && gc + 4 <= K) {
                v = *(const float4*)ap;
            } else {
                if (gc + 0 < K) v.x = ap[0];
                if (gc + 1 < K) v.y = ap[1];
                if (gc + 2 < K) v.z = ap[2];
                if (gc + 3 < K) v.w = ap[3];
            }
            uint32_t h0, l0, h1, l1;
            cvt_hilo(v.x, v.y, h0, l0);
            cvt_hilo(v.z, v.w, h1, l1);
            int w0 = (c4 * 2) ^ ((row & 7) << 2);
            *(uint2*)&sAh[row * WPR + w0] = make_uint2(h0, h1);
            *(uint2*)&sAl[row * WPR + w0] = make_uint2(l0, l1);
        }
        for (int idx = tid; idx < BN * (BK / 4); idx += NT) {
            int row = idx / (BK / 4), c4 = idx % (BK / 4);
            int gc = k0 + c4 * 4;
            float4 v = make_float4(0.f, 0.f, 0.f, 0.f);
            const float* bp = Bw + (size_t)(n0 + row) * K + gc;
            if (k4 && gc + 4 <= K) {
                v = *(const float4*)bp;
            } else {
                if (gc + 0 < K) v.x = bp[0];
                if (gc + 1 < K) v.y = bp[1];
                if (gc + 2 < K) v.z = bp[2];
                if (gc + 3 < K) v.w = bp[3];
            }
            uint32_t h0, l0, h1, l1;
            cvt_hilo(v.x, v.y, h0, l0);
            cvt_hilo(v.z, v.w, h1, l1);
            int w0 = (c4 * 2) ^ ((row & 7) << 2);
            *(uint2*)&sBh[row * WPR + w0] = make_uint2(h0, h1);
            *(uint2*)&sBl[row * WPR + w0] = make_uint2(l0, l1);
        }
        __syncthreads();
        const int sw = g << 2;
        const int ra0 = (wm * 16 + g) * WPR;
        const int ra1 = (wm * 16 + g + 8) * WPR;
#pragma unroll 4
        for (int c = 0; c < BK / 16; c++) {
            int ws0 = c * 8 + tig;
            uint32_t a0h = sAh[ra0 + (ws0 ^ sw)];
            uint32_t a1h = sAh[ra1 + (ws0 ^ sw)];
            uint32_t a2h = sAh[ra0 + ((ws0 + 4) ^ sw)];
            uint32_t a3h = sAh[ra1 + ((ws0 + 4) ^ sw)];
            uint32_t a0l = sAl[ra0 + (ws0 ^ sw)];
            uint32_t a1l = sAl[ra1 + (ws0 ^ sw)];
            uint32_t a2l = sAl[ra0 + ((ws0 + 4) ^ sw)];
            uint32_t a3l = sAl[ra1 + ((ws0 + 4) ^ sw)];
#pragma unroll
            for (int nt = 0; nt < 4; nt++) {
                int rb = (wn * 32 + nt * 8 + g) * WPR;
                uint32_t b0h = sBh[rb + (ws0 ^ sw)];
                uint32_t b1h = sBh[rb + ((ws0 + 4) ^ sw)];
                uint32_t b0l = sBl[rb + (ws0 ^ sw)];
                uint32_t b1l = sBl[rb + ((ws0 + 4) ^ sw)];
                mma16816(acc[nt], a0h, a1h, a2h, a3h, b0h, b1h);
                mma16816(acc[nt], a0h, a1h, a2h, a3h, b0l, b1l);
                mma16816(acc[nt], a0l, a1l, a2l, a3l, b0h, b1h);
            }
        }
        __syncthreads();
    }
#pragma unroll
    for (int nt = 0; nt < 4; nt++) {
        int col = n0 + wn * 32 + nt * 8 + 2 * tig;
        float b0v = __ldg(&bias[col]);
        float b1v = __ldg(&bias[col + 1]);
#pragma unroll
        for (int half = 0; half < 2; half++) {
            int r = m0 + wm * 16 + g + half * 8;
            int orow = KEYREMAP ? (r + (r >> 9)) : r;
            float x0 = acc[nt][half * 2 + 0] + b0v;
            float x1 = acc[nt][half * 2 + 1] + b1v;
            if (relu) { x0 = fmaxf(x0, 0.f); x1 = fmaxf(x1, 0.f); }
            *(float2*)&C[(size_t)orow * ldc + col] = make_float2(x0, x1);
        }
    }
}

// key GEMM wrapper: BK=128 -> 80KB smem -> 2 CTAs/SM
template <int WARPS_M, int WARPS_N, int BK, bool KEYREMAP>
__global__ void __launch_bounds__(256, 2)
gemm_k(const float* __restrict__ A, const float* __restrict__ Bw,
       float* __restrict__ C, const float* __restrict__ bias, int K, int ldc) {
    gemm_body<WARPS_M, WARPS_N, BK, KEYREMAP>(
        A, Bw, C, bias, K, ldc, false,
        blockIdx.x * WARPS_M * 16, blockIdx.y * WARPS_N * 32);
}
// gates GEMM wrapper (same config, no remap)
template <int WARPS_M, int WARPS_N, int BK>
__global__ void __launch_bounds__(256, 2)
gemm_g(const float* __restrict__ A, const float* __restrict__ Bw,
       float* __restrict__ C, const float* __restrict__ bias, int K, int ldc) {
    gemm_body<WARPS_M, WARPS_N, BK, false>(
        A, Bw, C, bias, K, ldc, false,
        blockIdx.x * WARPS_M * 16, blockIdx.y * WARPS_N * 32);
}
// dual small GEMM: z=0 -> pre10 (K=1024), z=1 -> func (K=259, relu)
__global__ void __launch_bounds__(256, 2)
gemm_dual(const float* A0, const float* B0, float* C0, const float* bias0, int K0,
          const float* A1, const float* B1, float* C1, const float* bias1, int K1) {
    if (blockIdx.z == 0)
        gemm_body<4, 2, 128, false>(A0, B0, C0, bias0, K0, 256, false,
                                    blockIdx.x * 64, blockIdx.y * 64);
    else
        gemm_body<4, 2, 128, false>(A1, B1, C1, bias1, K1, 256, true,
                                    blockIdx.x * 64, blockIdx.y * 64);
}

// ------- merged side precomputes: blocks 0..255 -> M/c1 row j; 256..383 -> wcomb
__global__ void k_side(const float* __restrict__ Wfc1,
                       const float* __restrict__ Wemb,
                       const float* __restrict__ bemb,
                       const float* __restrict__ Wfc2,
                       const float* __restrict__ bfc2,
                       const float* __restrict__ Wih,
                       const float* __restrict__ bih,
                       const float* __restrict__ bhh) {
    if (blockIdx.x < 256) {
        __shared__ float sred[8 * 32];
        __shared__ float sred1[8];
        int j = blockIdx.x;
        int lane = threadIdx.x & 31, w = threadIdx.x >> 5;
        const float* arow = Wfc1 + (size_t)j * 1024 + w * 128;
        float acc = 0.f;
#pragma unroll 8
        for (int i = 0; i < 128; i++) {
            float a = __ldg(&arow[i]);
            acc = fmaf(a, __ldg(&Wemb[(size_t)(w * 128 + i) * 32 + lane]), acc);
        }
        float a1 = 0.f;
#pragma unroll
        for (int q = 0; q < 4; q++) {
            int i = q * 32 + lane;
            a1 = fmaf(__ldg(&arow[i]), __ldg(&bemb[w * 128 + i]), a1);
        }
#pragma unroll
        for (int off = 16; off > 0; off >>= 1)
            a1 += __shfl_xor_sync(0xffffffffu, a1, off);
        if (lane == 0) sred1[w] = a1;
        sred[w * 32 + lane] = acc;
        __syncthreads();
        if (threadIdx.x < 32) {
            float s = 0.f;
#pragma unroll
            for (int gp = 0; gp < 8; gp++) s += sred[gp * 32 + threadIdx.x];
            g_M[j * 32 + threadIdx.x] = s;
            if (threadIdx.x == 0) {
                float s1 = 0.f;
#pragma unroll
                for (int gp = 0; gp < 8; gp++) s1 += sred1[gp];
                g_c1[j] = s1;
            }
        }
    } else {
        __shared__ float sWih[32];
        int gi = blockIdx.x - 256;
        int tid = threadIdx.x;
        if (tid < 32) sWih[tid] = Wih[gi * 32 + tid];
        __syncthreads();
        float acc = 0.f;
#pragma unroll
        for (int k = 0; k < 32; k++)
            acc = fmaf(sWih[k], __ldg(&Wfc2[k * 256 + tid]), acc);
        g_wcomb[gi * 256 + tid] = acc;
        if (tid == 0) {
            float b = bih[gi] + bhh[gi];
#pragma unroll
            for (int k = 0; k < 32; k++) b = fmaf(sWih[k], bfc2[k], b);
            g_gbias[gi] = b;
        }
    }
}

// -------- availability thresholds + selected-key prefix sums + end rows ----
__global__ void k_prep(const float* __restrict__ avail,
                       const int* __restrict__ selected,
                       const float* __restrict__ endv) {
    __shared__ int s_thr[NP1];
    int b = blockIdx.x;
    int lane = threadIdx.x;  // 32 threads
    g_padkey[((size_t)b * NP1 + 512) * 32 + lane] = endv[lane];
    for (int n = lane; n < NP1; n += 32)
        s_thr[n] = (n == 512) ? 33 : (avail[(size_t)b * 512 + n] > 0.5f ? 33 : -1);
    __syncwarp();
    int selv = selected[b * 32 + lane];
    float rr[32];
#pragma unroll
    for (int t = 0; t < 32; t++) {
        int s = __shfl_sync(0xffffffffu, selv, t);
        rr[t] = __ldg(&g_padkey[((size_t)b * NP1 + s) * 32 + lane]);
    }
    float acc = 0.f;
    const float inv_n = 1.0f / 512.0f;
#pragma unroll
    for (int t = 0; t < 32; t++) {
        g_prefix[((size_t)b * TT + t) * 32 + lane] = acc;
        acc = fmaf(rr[t], inv_n, acc);
        int s = __shfl_sync(0xffffffffu, selv, t);
        if (lane == 0) {
            int v = s_thr[s];
            if (v < 0 || v >= 32) s_thr[s] = t;
        }
    }
    __syncwarp();
    g_prefix[((size_t)b * TT + 32) * 32 + lane] = acc;
    for (int n = lane; n < NP1; n += 32)
        g_thr[(size_t)b * NP1 + n] = s_thr[n];
}

// -------- relu_a[b,t,:] = relu(pre10 + func + t*c1 + prefix_t @ M^T) --------
__global__ void k_gA() {
    __shared__ float sp[TT * 32];
    int b = blockIdx.x, tid = threadIdx.x;
    for (int i = tid; i < TT * 32; i += 256) sp[i] = g_prefix[(size_t)b * TT * 32 + i];
    float pre = g_pre10[(size_t)b * 256 + tid] + g_func[(size_t)b * 256 + tid];
    float c1 = g_c1[tid];
    float m[32];
    const float4* mr = reinterpret_cast<const float4*>(g_M + tid * 32);
#pragma unroll
    for (int q = 0; q < 8; q++) {
        float4 v = __ldg(mr + q);
        m[q * 4 + 0] = v.x; m[q * 4 + 1] = v.y; m[q * 4 + 2] = v.z; m[q * 4 + 3] = v.w;
    }
    __syncthreads();
    for (int t = 0; t < TT; t++) {
        float acc = fmaf((float)t, c1, pre);
        const float* p = &sp[t * 32];
#pragma unroll
        for (int k = 0; k < 32; k++) acc = fmaf(m[k], p[k], acc);
        g_relua[((size_t)b * TT + t) * 256 + tid] = fmaxf(acc, 0.f);
    }
}

// ---------------- LSTM recurrence -----------
__global__ void k_lstm(const float* __restrict__ Whh) {
    __shared__ float sW[128 * 33];
    __shared__ float s_h[32];
    __shared__ float s_c[32];
    __shared__ float s_g[128];
    int b = blockIdx.x, tid = threadIdx.x;
    for (int idx = tid; idx < 128 * 32; idx += 128) {
        int gg2 = idx >> 5, kk = idx & 31;
        sW[gg2 * 33 + kk] = Whh[idx];
    }
    if (tid < 32) { s_h[tid] = 0.f; s_c[tid] = 0.f; }
    __syncthreads();
    for (int t = 0; t < TT; t++) {
        float gg = g_gx[((size_t)b * TT + t) * 128 + tid];
        const float* wrow = &sW[tid * 33];
#pragma unroll
        for (int kk = 0; kk < 32; kk++) gg = fmaf(wrow[kk], s_h[kk], gg);
        s_g[tid] = gg;
        __syncthreads();
        if (tid < 32) {
            float ig = sigmoidf_(s_g[tid]);
            float fg = sigmoidf_(s_g[32 + tid]);
            float gt = tanhf(s_g[64 + tid]);
            float og = sigmoidf_(s_g[96 + tid]);
            float c = fmaf(fg, s_c[tid], ig * gt);
            float h = og * tanhf(c);
            s_c[tid] = c;
            s_h[tid] = h;
            g_h[((size_t)b * TT + t) * 32 + tid] = h;
        }
        __syncthreads();
    }
}

// ---------------- logits[b,t,n] = h_t . key_n - mask --------------------
__global__ void k_logits(float* __restrict__ out) {
    __shared__ float s_h[TT * 32];
    __shared__ float s_key[128 * 36];
    int b = blockIdx.y, n0 = blockIdx.x * 128, tid = threadIdx.x;
    for (int idx = tid; idx < TT * 32; idx += 256)
        s_h[idx] = g_h[(size_t)b * (TT * 32) + idx];
    int nmax = NP1 - n0; if (nmax > 128) nmax = 128;
    for (int idx = tid; idx < nmax * 32; idx += 256) {
        int r = idx >> 5, kk = idx & 31;
        s_key[r * 36 + kk] = g_padkey[((size_t)(b * NP1 + n0)) * 32 + idx];
    }
    __syncthreads();
    int nn = tid & 127, ts = tid >> 7;
    if (nn < nmax) {
        int n = n0 + nn;
        float4 kr[8];
        const float4* k4 = reinterpret_cast<const float4*>(&s_key[nn * 36]);
#pragma unroll
        for (int q = 0; q < 8; q++) kr[q] = k4[q];
        int thr = g_thr[(size_t)b * NP1 + n];
        for (int t = ts; t < TT; t += 2) {
            const float4* h4 = reinterpret_cast<const float4*>(&s_h[t * 32]);
            float acc = 0.f;
#pragma unroll
            for (int q = 0; q < 8; q++) acc += dot4(h4[q], kr[q]);
            out[((size_t)b * TT + t) * NP1 + n] = acc - (t > thr ? 1e9f : 0.f);
        }
    }
}

// ---------------- final emb output ---------------------------------------
__global__ void k_emb(float* __restrict__ out,
                      const float* __restrict__ emb0,
                      const float* __restrict__ Wemb,
                      const float* __restrict__ bemb) {
    __shared__ float s_p[32];
    int b = blockIdx.x, tid = threadIdx.x;
    if (tid < 32) s_p[tid] = g_prefix[((size_t)b * TT + 32) * 32 + tid];
    __syncthreads();
    const float4* p4 = reinterpret_cast<const float4*>(s_p);
#pragma unroll
    for (int q = 0; q < 4; q++) {
        int i = q * 256 + tid;
        const float4* we = reinterpret_cast<const float4*>(Wemb + (size_t)i * 32);
        float acc = __ldg(&emb0[(size_t)b * 1024 + i]) + 32.0f * __ldg(&bemb[i]);
#pragma unroll
        for (int r = 0; r < 8; r++) acc += dot4(__ldg(we + r), p4[r]);
        out[LOGITS_ELEMS + (size_t)b * 1024 + i] = acc;
    }
}

// ---------------- launch -----------------------------------------------------
extern "C" void kernel_launch(void* const* d_in, const int* in_sizes, int n_in,
                              void* d_out, int out_size) {
    const float* embedding = (const float*)d_in[0];
    const float* type_mask = (const float*)d_in[1];
    const float* avail     = (const float*)d_in[2];
    const float* ent       = (const float*)d_in[3];
    const int*   selected  = (const int*)d_in[4];
    const float* endv      = (const float*)d_in[5];
    const float* W_key  = (const float*)d_in[6];
    const float* b_key  = (const float*)d_in[7];
    const float* W_func = (const float*)d_in[8];
    const float* b_func = (const float*)d_in[9];
    const float* W_fc1  = (const float*)d_in[10];
    const float* b_fc1  = (const float*)d_in[11];
    const float* W_fc2  = (const float*)d_in[12];
    const float* b_fc2  = (const float*)d_in[13];
    const float* W_emb  = (const float*)d_in[14];
    const float* b_emb  = (const float*)d_in[15];
    const float* W_ih   = (const float*)d_in[16];
    const float* b_ih   = (const float*)d_in[17];
    const float* W_hh   = (const float*)d_in[18];
    const float* b_hh   = (const float*)d_in[19];
    float* out = (float*)d_out;

    // smem: (8,1,128): 2*(128+32)*64*4 = 81920 B -> 2 CTAs/SM
    //       (4,2,128): 2*(64+64)*64*4  = 65536 B
    const int SMB = 81920, SM2 = 65536;
    cudaFuncSetAttribute(gemm_k<8, 1, 128, true>,
                         cudaFuncAttributeMaxDynamicSharedMemorySize, SMB);
    cudaFuncSetAttribute(gemm_g<8, 1, 128>,
                         cudaFuncAttributeMaxDynamicSharedMemorySize, SMB);
    cudaFuncSetAttribute(gemm_dual,
                         cudaFuncAttributeMaxDynamicSharedMemorySize, SM2);

    float* padkey; cudaGetSymbolAddress((void**)&padkey, g_padkey);
    float* pre10;  cudaGetSymbolAddress((void**)&pre10, g_pre10);
    float* funcb;  cudaGetSymbolAddress((void**)&funcb, g_func);
    float* relua;  cudaGetSymbolAddress((void**)&relua, g_relua);
    float* gx;     cudaGetSymbolAddress((void**)&gx, g_gx);
    float* wcomb;  cudaGetSymbolAddress((void**)&wcomb, g_wcomb);
    float* gbias;  cudaGetSymbolAddress((void**)&gbias, g_gbias);

    cudaStream_t s1;
    cudaStreamCreateWithFlags(&s1, cudaStreamNonBlocking);
    cudaEvent_t evFork, evS1, evPrep, evEmb;
    cudaEventCreateWithFlags(&evFork, cudaEventDisableTiming);
    cudaEventCreateWithFlags(&evS1, cudaEventDisableTiming);
    cudaEventCreateWithFlags(&evPrep, cudaEventDisableTiming);
    cudaEventCreateWithFlags(&evEmb, cudaEventDisableTiming);

    // ---- fork: side branch (independent of the big key GEMM) ----
    cudaEventRecord(evFork, 0);
    cudaStreamWaitEvent(s1, evFork, 0);
    gemm_dual<<<dim3(4, 4, 2), 256, SM2, s1>>>(
        embedding, W_fc1, pre10, b_fc1, 1024,
        type_mask, W_func, funcb, b_func, DTY);
    k_side<<<384, 256, 0, s1>>>(W_fc1, W_emb, b_emb, W_fc2, b_fc2, W_ih, b_ih, b_hh);
    cudaEventRecord(evS1, s1);

    // ---- main stream: key GEMM -> prep ----
    gemm_k<8, 1, 128, true>
        <<<dim3(BB * NN / 128, 1), 256, SMB>>>(ent, W_key, padkey, b_key, 256, 32);
    k_prep<<<BB, 32>>>(avail, selected, endv);
    cudaEventRecord(evPrep, 0);

    // ---- k_emb only needs g_prefix: run on side stream ----
    cudaStreamWaitEvent(s1, evPrep, 0);
    k_emb<<<BB, 256, 0, s1>>>(out, embedding, W_emb, b_emb);
    cudaEventRecord(evEmb, s1);

    // ---- main chain continues after side precomputes land ----
    cudaStreamWaitEvent(0, evS1, 0);
    k_gA<<<BB, 256>>>();
    gemm_g<8, 1, 128>
        <<<dim3(BB * TT / 128, 4), 256, SMB>>>(relua, wcomb, gx, gbias, 256, 128);
    k_lstm<<<BB, 128>>>(W_hh);
    k_logits<<<dim3(5, BB), 256>>>(out);

    // ---- join ----
    cudaStreamWaitEvent(0, evEmb, 0);
}